// round 5
// baseline (speedup 1.0000x reference)
#include <cuda_runtime.h>
#include <math.h>

#define MAX_NODES 100000
#define F_DIM 128
#define P_COLS 256   // [PW_src(64) | PA_src(64) | PW_dst(64) | PA_dst(64)]

__device__ float g_P[(size_t)MAX_NODES * P_COLS];

// ---------------- packed f32x2 helpers (sm_103a FFMA2) ----------------
typedef unsigned long long ull;
__device__ __forceinline__ ull pack2(float x, float y) {
    ull r; asm("mov.b64 %0, {%1,%2};" : "=l"(r) : "f"(x), "f"(y)); return r;
}
__device__ __forceinline__ void unpack2(ull v, float& x, float& y) {
    asm("mov.b64 {%0,%1}, %2;" : "=f"(x), "=f"(y) : "l"(v));
}
__device__ __forceinline__ ull fma2(ull a, ull b, ull c) {
    ull d; asm("fma.rn.f32x2 %0, %1, %2, %3;" : "=l"(d) : "l"(a), "l"(b), "l"(c)); return d;
}
__device__ __forceinline__ ull dbits(double d) { return __double_as_longlong(d); }

// ---------------------------------------------------------------------------
// Kernel 1 (v3): P[n,:] = x[n,:] @ [W1top | A1top | W1bot | A1bot]
// 128m x 64n tile, 256 threads, 8m x 4n per thread, FFMA2, k-major Xs.
// Dynamic smem: Xs[64][132] + Bs[64][64] = 50176 B.
// ---------------------------------------------------------------------------
#define XPITCH 132
__global__ __launch_bounds__(256, 2)
void precompute_kernel3(const float* __restrict__ x,
                        const float* __restrict__ W1,
                        const float* __restrict__ A1,
                        int n_nodes) {
    extern __shared__ float psm[];
    float* Xs = psm;                 // [64][132]
    float* Bs = psm + 64 * XPITCH;   // [64][64]

    const int tid = threadIdx.x;
    const int m0b = blockIdx.x * 128;
    const int n0b = blockIdx.y * 64;
    const int tx = tid & 15;
    const int ty = tid >> 4;
    const int m0 = ty * 8;
    const int n0 = tx * 4;

    ull acc[4][4];
    #pragma unroll
    for (int i = 0; i < 4; i++)
        #pragma unroll
        for (int j = 0; j < 4; j++) acc[i][j] = 0ull;

    for (int k0 = 0; k0 < F_DIM; k0 += 64) {
        // X tile -> k-major smem (coalesced LDG, padded pitch)
        #pragma unroll
        for (int t = 0; t < 32; t++) {
            int i = tid + t * 256;          // 0..8191
            int m = i >> 6, k = i & 63;
            int gm = m0b + m;
            Xs[k * XPITCH + m] = (gm < n_nodes) ? x[(size_t)gm * F_DIM + k0 + k] : 0.f;
        }
        // B tile ([W1top|A1top|W1bot|A1bot] materialized on the fly)
        #pragma unroll
        for (int t = 0; t < 16; t++) {
            int i = tid + t * 256;          // 0..4095
            int k = i >> 6, n = i & 63;
            int c = n0b + n;
            int g = c >> 6;
            int j = c & 63;
            int krow = k0 + k;
            float v;
            if (g == 0)      v = W1[(size_t)krow * 64 + j];
            else if (g == 1) v = A1[(size_t)krow * 64 + j];
            else if (g == 2) v = W1[(size_t)(128 + krow) * 64 + j];
            else             v = A1[(size_t)(128 + krow) * 64 + j];
            Bs[k * 64 + n] = v;
        }
        __syncthreads();

        #pragma unroll 16
        for (int kk = 0; kk < 64; kk++) {
            const double2 av0 = *(const double2*)(Xs + kk * XPITCH + m0);
            const double2 av1 = *(const double2*)(Xs + kk * XPITCH + m0 + 4);
            const float4  bv  = *(const float4*)(Bs + kk * 64 + n0);
            ull ar[4] = { dbits(av0.x), dbits(av0.y), dbits(av1.x), dbits(av1.y) };
            ull bd[4] = { pack2(bv.x, bv.x), pack2(bv.y, bv.y),
                          pack2(bv.z, bv.z), pack2(bv.w, bv.w) };
            #pragma unroll
            for (int i = 0; i < 4; i++)
                #pragma unroll
                for (int j = 0; j < 4; j++)
                    acc[i][j] = fma2(ar[i], bd[j], acc[i][j]);
        }
        __syncthreads();
    }

    #pragma unroll
    for (int i = 0; i < 4; i++) {
        float r0[4], r1[4];
        #pragma unroll
        for (int j = 0; j < 4; j++) unpack2(acc[i][j], r0[j], r1[j]);
        int gm0 = m0b + m0 + 2 * i;
        if (gm0 < n_nodes)
            *(float4*)(&g_P[(size_t)gm0 * P_COLS + n0b + n0]) = make_float4(r0[0], r0[1], r0[2], r0[3]);
        if (gm0 + 1 < n_nodes)
            *(float4*)(&g_P[(size_t)(gm0 + 1) * P_COLS + n0b + n0]) = make_float4(r1[0], r1[1], r1[2], r1[3]);
    }
}

// ---------------------------------------------------------------------------
// Kernel 2 (v4): 256 edges/block, 256 threads, 16m x 4n micro-tile.
// smem (dynamic, 103424 B):
//   sm_h1 : [64][256] swizzled k-major        (16384 floats)
//   sm_X  : union { Wc [64][64] ; h2 [32][264] swizzled }  (8448 floats)
//   sm_w3 : [32][32] = [W3|A3]                (1024 floats)
// h1 swizzle:  phys(j,e) = j*256 + ((e>>2)^(j>>2))*4 + (e&3)
// h2 swizzle:  phys(n,m) = n*264 + (m ^ (((n>>2)&3)<<2))
// ---------------------------------------------------------------------------
#define TILE_E 256
#define H1P 256
#define H2P 264

__global__ __launch_bounds__(256, 2)
void edge_kernel4(const int* __restrict__ ei,
                  const float* __restrict__ b1,
                  const float* __restrict__ W2, const float* __restrict__ b2,
                  const float* __restrict__ A2,
                  const float* __restrict__ W3, const float* __restrict__ b3,
                  const float* __restrict__ A3,
                  const float* __restrict__ Wf, const float* __restrict__ bf,
                  float* __restrict__ out, int E) {
    extern __shared__ float sm[];
    float* sm_h1 = sm;                    // 16384
    float* sm_X  = sm + 16384;            // 8448 (Wc then h2)
    float* sm_w3 = sm + 16384 + 8448;     // 1024

    const int tid = threadIdx.x;
    const int e_base = blockIdx.x * TILE_E;
    const int warp = tid >> 5;
    const int lane = tid & 31;

    // ---- weight staging ----
    #pragma unroll
    for (int t = 0; t < 16; t++) {
        int i = tid + t * 256;
        int k = i >> 6, n = i & 63;
        sm_X[k * 64 + n] = (n < 32) ? W2[k * 32 + n] : A2[k * 32 + (n - 32)];
    }
    #pragma unroll
    for (int t = 0; t < 4; t++) {
        int i = tid + t * 256;
        int k = i >> 5, n = i & 31;
        sm_w3[k * 32 + n] = (n < 16) ? W3[k * 16 + n] : A3[k * 16 + (n - 16)];
    }

    // ---- Stage A: coalesced gather + layer1, 32 edges per warp ----
    {
        const int l15 = lane & 15;
        int idxA = 0, idxB = 0;
        {
            int eg0 = e_base + warp * 32 + l15;
            int eg1 = eg0 + 16;
            if (lane < 16) {
                if (eg0 < E) idxA = ei[eg0];
                if (eg1 < E) idxB = ei[eg1];
            } else {
                if (eg0 < E) idxA = ei[(size_t)E + eg0];
                if (eg1 < E) idxB = ei[(size_t)E + eg1];
            }
            idxA = min(max(idxA, 0), MAX_NODES - 1);
            idxB = min(max(idxB, 0), MAX_NODES - 1);
        }
        const float4 b1v = *(const float4*)(b1 + 4 * l15);
        const bool lo = (lane < 16);

        #pragma unroll
        for (int p = 0; p < 16; p++) {
            const int q = 2 * (p & 7);
            const int srcA = __shfl_sync(0xffffffffu, (p < 8) ? idxA : idxB, q);
            const int dstA = __shfl_sync(0xffffffffu, (p < 8) ? idxA : idxB, 16 + q);
            const int srcB = __shfl_sync(0xffffffffu, (p < 8) ? idxA : idxB, q + 1);
            const int dstB = __shfl_sync(0xffffffffu, (p < 8) ? idxA : idxB, 17 + q);

            const float4 sA = *(const float4*)(g_P + (size_t)srcA * P_COLS + lane * 4);
            const float4 dA = *(const float4*)(g_P + (size_t)dstA * P_COLS + 128 + lane * 4);
            const float4 sB = *(const float4*)(g_P + (size_t)srcB * P_COLS + lane * 4);
            const float4 dB = *(const float4*)(g_P + (size_t)dstB * P_COLS + 128 + lane * 4);

            float4 wA, wB;
            wA.x = sA.x + dA.x; wA.y = sA.y + dA.y; wA.z = sA.z + dA.z; wA.w = sA.w + dA.w;
            wB.x = sB.x + dB.x; wB.y = sB.y + dB.y; wB.z = sB.z + dB.z; wB.w = sB.w + dB.w;

            // single exchange: lo lanes send wB (B's W-half) and receive wA's A-half
            float4 t, o;
            t.x = lo ? wB.x : wA.x;  t.y = lo ? wB.y : wA.y;
            t.z = lo ? wB.z : wA.z;  t.w = lo ? wB.w : wA.w;
            o.x = __shfl_xor_sync(0xffffffffu, t.x, 16);
            o.y = __shfl_xor_sync(0xffffffffu, t.y, 16);
            o.z = __shfl_xor_sync(0xffffffffu, t.z, 16);
            o.w = __shfl_xor_sync(0xffffffffu, t.w, 16);

            float4 w, a;
            w.x = lo ? wA.x : o.x;  a.x = lo ? o.x : wB.x;
            w.y = lo ? wA.y : o.y;  a.y = lo ? o.y : wB.y;
            w.z = lo ? wA.z : o.z;  a.z = lo ? o.z : wB.z;
            w.w = lo ? wA.w : o.w;  a.w = lo ? o.w : wB.w;

            float h0  = fmaxf(fmaxf(w.x + b1v.x, 0.f) + a.x, 0.f);
            float h1v = fmaxf(fmaxf(w.y + b1v.y, 0.f) + a.y, 0.f);
            float h2v = fmaxf(fmaxf(w.z + b1v.z, 0.f) + a.z, 0.f);
            float h3v = fmaxf(fmaxf(w.w + b1v.w, 0.f) + a.w, 0.f);

            const int e_loc = warp * 32 + 2 * p + (lo ? 0 : 1);
            const int col = (e_loc >> 2) ^ l15;
            float* qp = sm_h1 + (4 * l15) * H1P + col * 4 + (e_loc & 3);
            qp[0]       = h0;
            qp[H1P]     = h1v;
            qp[2 * H1P] = h2v;
            qp[3 * H1P] = h3v;
        }
    }
    __syncthreads();

    // ---- Stage B: layer2 GEMM, [256 m] x [64 n = W2|A2] x [64 k] ----
    const int tx = tid & 15;
    const int ty = tid >> 4;
    const int m0 = ty * 16;
    const int n0 = tx * 4;

    ull acc[8][4];
    #pragma unroll
    for (int ip = 0; ip < 8; ip++)
        #pragma unroll
        for (int c = 0; c < 4; c++) acc[ip][c] = 0ull;

    #pragma unroll 16
    for (int k = 0; k < 64; k++) {
        const int xr = k >> 2;
        const float* base = sm_h1 + k * H1P;
        const double2 A0 = *(const double2*)(base + (((4 * ty + 0) ^ xr) << 2));
        const double2 A1 = *(const double2*)(base + (((4 * ty + 1) ^ xr) << 2));
        const double2 A2v = *(const double2*)(base + (((4 * ty + 2) ^ xr) << 2));
        const double2 A3v = *(const double2*)(base + (((4 * ty + 3) ^ xr) << 2));
        const float4 b = *(const float4*)(sm_X + k * 64 + n0);
        ull ar[8] = { dbits(A0.x), dbits(A0.y), dbits(A1.x), dbits(A1.y),
                      dbits(A2v.x), dbits(A2v.y), dbits(A3v.x), dbits(A3v.y) };
        ull bd[4] = { pack2(b.x, b.x), pack2(b.y, b.y), pack2(b.z, b.z), pack2(b.w, b.w) };
        #pragma unroll
        for (int ip = 0; ip < 8; ip++)
            #pragma unroll
            for (int c = 0; c < 4; c++)
                acc[ip][c] = fma2(ar[ip], bd[c], acc[ip][c]);
    }
    __syncthreads();   // all Wc reads done before h2 overwrites sm_X

    // combine W/A halves; tx<8 holds h2 for n = n0..n0+3, m = m0..m0+15
    const int sig2 = (tx & 3) << 2;    // h2 swizzle for this thread's n-cols
    #pragma unroll
    for (int ip = 0; ip < 8; ip++) {
        #pragma unroll
        for (int c = 0; c < 4; c++) {
            ull other = __shfl_down_sync(0xffffffffu, acc[ip][c], 8);
            if (tx < 8) {
                float wlo, whi, alo, ahi;
                unpack2(acc[ip][c], wlo, whi);
                unpack2(other, alo, ahi);
                float bb = __ldg(b2 + n0 + c);
                float v0 = fmaxf(fmaxf(wlo + bb, 0.f) + alo, 0.f);
                float v1 = fmaxf(fmaxf(whi + bb, 0.f) + ahi, 0.f);
                int m = m0 + 2 * ip;
                *(float2*)(sm_X + (n0 + c) * H2P + (m ^ sig2)) = make_float2(v0, v1);
            }
        }
    }
    __syncwarp();   // h2 producer/consumer is warp-local

    // ---- Stage C: layer3 GEMM [256 m] x [32 = W3|A3] x [32 k] + head ----
    const int n0c = tx * 2;
    ull acc3[8][2];
    #pragma unroll
    for (int ip = 0; ip < 8; ip++) { acc3[ip][0] = 0ull; acc3[ip][1] = 0ull; }

    #pragma unroll 8
    for (int k = 0; k < 32; k++) {
        const int sk = ((k >> 2) & 3) << 2;
        const float* base = sm_X + k * H2P;
        const double2 A0 = *(const double2*)(base + ((m0 + 0) ^ sk));
        const double2 A1 = *(const double2*)(base + ((m0 + 4) ^ sk));
        const double2 A2v = *(const double2*)(base + ((m0 + 8) ^ sk));
        const double2 A3v = *(const double2*)(base + ((m0 + 12) ^ sk));
        const float2 b = *(const float2*)(sm_w3 + k * 32 + n0c);
        ull ar[8] = { dbits(A0.x), dbits(A0.y), dbits(A1.x), dbits(A1.y),
                      dbits(A2v.x), dbits(A2v.y), dbits(A3v.x), dbits(A3v.y) };
        ull bd0 = pack2(b.x, b.x);
        ull bd1 = pack2(b.y, b.y);
        #pragma unroll
        for (int ip = 0; ip < 8; ip++) {
            acc3[ip][0] = fma2(ar[ip], bd0, acc3[ip][0]);
            acc3[ip][1] = fma2(ar[ip], bd1, acc3[ip][1]);
        }
    }

    float p[16];
    #pragma unroll
    for (int i = 0; i < 16; i++) p[i] = 0.f;

    #pragma unroll
    for (int ip = 0; ip < 8; ip++) {
        #pragma unroll
        for (int c = 0; c < 2; c++) {
            ull other = __shfl_down_sync(0xffffffffu, acc3[ip][c], 8);
            if (tx < 8) {
                float wlo, whi, alo, ahi;
                unpack2(acc3[ip][c], wlo, whi);
                unpack2(other, alo, ahi);
                int n = n0c + c;                 // 0..15
                float bb = __ldg(b3 + n);
                float wf = __ldg(Wf + n);
                float h3lo = fmaxf(fmaxf(wlo + bb, 0.f) + alo, 0.f);
                float h3hi = fmaxf(fmaxf(whi + bb, 0.f) + ahi, 0.f);
                p[2 * ip]     += h3lo * wf;
                p[2 * ip + 1] += h3hi * wf;
            }
        }
    }

    #pragma unroll
    for (int o = 1; o < 8; o <<= 1) {
        #pragma unroll
        for (int i = 0; i < 16; i++)
            p[i] += __shfl_xor_sync(0xffffffffu, p[i], o);
    }

    if (tx == 0) {
        float bfv = __ldg(bf);
        float r[16];
        #pragma unroll
        for (int i = 0; i < 16; i++)
            r[i] = 1.f / (1.f + expf(-(p[i] + bfv)));
        int eg = e_base + m0;
        if (eg + 15 < E) {
            #pragma unroll
            for (int v = 0; v < 4; v++)
                *(float4*)(out + eg + 4 * v) = make_float4(r[4 * v], r[4 * v + 1], r[4 * v + 2], r[4 * v + 3]);
        } else {
            #pragma unroll
            for (int i = 0; i < 16; i++)
                if (eg + i < E) out[eg + i] = r[i];
        }
    }
}

// ---------------------------------------------------------------------------
extern "C" void kernel_launch(void* const* d_in, const int* in_sizes, int n_in,
                              void* d_out, int out_size) {
    const float* x  = (const float*)d_in[0];
    const int*   ei = (const int*)d_in[1];
    const float* W1 = (const float*)d_in[2];
    const float* b1 = (const float*)d_in[3];
    const float* A1 = (const float*)d_in[4];
    const float* W2 = (const float*)d_in[5];
    const float* b2 = (const float*)d_in[6];
    const float* A2 = (const float*)d_in[7];
    const float* W3 = (const float*)d_in[8];
    const float* b3 = (const float*)d_in[9];
    const float* A3 = (const float*)d_in[10];
    const float* Wf = (const float*)d_in[11];
    const float* bf = (const float*)d_in[12];
    float* out = (float*)d_out;

    const int n_nodes = in_sizes[0] / F_DIM;
    const int E = in_sizes[1] / 2;

    const int pre_smem = (64 * XPITCH + 64 * 64) * 4;   // 50176
    cudaFuncSetAttribute(precompute_kernel3, cudaFuncAttributeMaxDynamicSharedMemorySize, pre_smem);
    dim3 g1((n_nodes + 127) / 128, 4);
    precompute_kernel3<<<g1, 256, pre_smem>>>(x, W1, A1, n_nodes);

    const int smem_bytes = (16384 + 8448 + 1024) * 4;   // 103424
    cudaFuncSetAttribute(edge_kernel4, cudaFuncAttributeMaxDynamicSharedMemorySize, smem_bytes);
    const int nb = (E + TILE_E - 1) / TILE_E;
    edge_kernel4<<<nb, 256, smem_bytes>>>(ei, b1, W2, b2, A2, W3, b3, A3, Wf, bf, out, E);
}

// round 7
// speedup vs baseline: 1.1948x; 1.1948x over previous
#include <cuda_runtime.h>
#include <math.h>

#define MAX_NODES 100000
#define F_DIM 128
#define P_COLS 256   // [PW_src(64) | PA_src(64) | PW_dst(64) | PA_dst(64)]

__device__ float g_P[(size_t)MAX_NODES * P_COLS];

// ---------------- packed f32x2 helpers (sm_103a FFMA2) ----------------
typedef unsigned long long ull;
__device__ __forceinline__ ull pack2(float x, float y) {
    ull r; asm("mov.b64 %0, {%1,%2};" : "=l"(r) : "f"(x), "f"(y)); return r;
}
__device__ __forceinline__ void unpack2(ull v, float& x, float& y) {
    asm("mov.b64 {%0,%1}, %2;" : "=f"(x), "=f"(y) : "l"(v));
}
__device__ __forceinline__ ull fma2(ull a, ull b, ull c) {
    ull d; asm("fma.rn.f32x2 %0, %1, %2, %3;" : "=l"(d) : "l"(a), "l"(b), "l"(c)); return d;
}
__device__ __forceinline__ ull dbits(double d) { return __double_as_longlong(d); }

// ---------------------------------------------------------------------------
// Kernel 1 (v4b): P[n,:] = x[n,:] @ [W1top | A1top | W1bot | A1bot]
// ONE block per 128-node tile. Xs loaded ONCE (k-major, [128][132]), then the
// 4 output quadrants produced in sequence; each quadrant's B is a contiguous
// 32KB slice of W1/A1 (plain memcpy into Bs[128][64]).
// XP=132: divisible by 4 (double2-aligned columns) and odd in 16B groups
// (conflict-free). smem = (128*132 + 128*64)*4 = 100352 B -> 2 blocks/SM.
// ---------------------------------------------------------------------------
#define XP 132
__global__ __launch_bounds__(256, 2)
void precompute_kernel4(const float* __restrict__ x,
                        const float* __restrict__ W1,
                        const float* __restrict__ A1,
                        int n_nodes) {
    extern __shared__ float psm[];
    float* Xs = psm;                 // [k=128][m=128], pitch 132
    float* Bs = psm + 128 * XP;      // [k=128][n=64]

    const int tid = threadIdx.x;
    const int m0b = blockIdx.x * 128;
    const int tx = tid & 15;
    const int ty = tid >> 4;
    const int m0 = ty * 8;
    const int n0 = tx * 4;

    // ---- load X tile once: coalesced LDG rows -> k-major smem ----
    #pragma unroll
    for (int t = 0; t < 64; t++) {
        int i = tid + t * 256;          // 0..16383
        int m = i >> 7, k = i & 127;
        int gm = m0b + m;
        Xs[k * XP + m] = (gm < n_nodes) ? x[(size_t)gm * F_DIM + k] : 0.f;
    }

    for (int q = 0; q < 4; q++) {
        __syncthreads();   // q=0: Xs ready; q>0: prior Bs reads done
        // quadrant q source: q0=W1[0:128], q1=A1[0:128], q2=W1[128:], q3=A1[128:]
        const float* srcq = ((q & 1) ? A1 : W1) + (size_t)(q >> 1) * 128 * 64;
        #pragma unroll
        for (int t = 0; t < 32; t++) {
            int i = tid + t * 256;      // 0..8191 contiguous copy
            Bs[i] = srcq[i];
        }
        __syncthreads();

        ull acc[4][4];
        #pragma unroll
        for (int i = 0; i < 4; i++)
            #pragma unroll
            for (int j = 0; j < 4; j++) acc[i][j] = 0ull;

        #pragma unroll 32
        for (int kk = 0; kk < 128; kk++) {
            const double2 av0 = *(const double2*)(Xs + kk * XP + m0);
            const double2 av1 = *(const double2*)(Xs + kk * XP + m0 + 4);
            const float4  bv  = *(const float4*)(Bs + kk * 64 + n0);
            ull ar[4] = { dbits(av0.x), dbits(av0.y), dbits(av1.x), dbits(av1.y) };
            ull bd[4] = { pack2(bv.x, bv.x), pack2(bv.y, bv.y),
                          pack2(bv.z, bv.z), pack2(bv.w, bv.w) };
            #pragma unroll
            for (int i = 0; i < 4; i++)
                #pragma unroll
                for (int j = 0; j < 4; j++)
                    acc[i][j] = fma2(ar[i], bd[j], acc[i][j]);
        }

        #pragma unroll
        for (int i = 0; i < 4; i++) {
            float r0[4], r1[4];
            #pragma unroll
            for (int j = 0; j < 4; j++) unpack2(acc[i][j], r0[j], r1[j]);
            int gm0 = m0b + m0 + 2 * i;
            if (gm0 < n_nodes)
                *(float4*)(&g_P[(size_t)gm0 * P_COLS + q * 64 + n0]) =
                    make_float4(r0[0], r0[1], r0[2], r0[3]);
            if (gm0 + 1 < n_nodes)
                *(float4*)(&g_P[(size_t)(gm0 + 1) * P_COLS + q * 64 + n0]) =
                    make_float4(r1[0], r1[1], r1[2], r1[3]);
        }
    }
}

// ---------------------------------------------------------------------------
// Kernel 2 (v5 = R4 structure + grouped-swizzle k-loops): 128 edges/block.
// smem 53760 B -> 4 blocks/SM.
// ---------------------------------------------------------------------------
#define TILE_E 128
#define H1_PITCH 128
#define H2_PITCH 132

__global__ __launch_bounds__(256, 4)
void edge_kernel5(const int* __restrict__ ei,
                  const float* __restrict__ b1,
                  const float* __restrict__ W2, const float* __restrict__ b2,
                  const float* __restrict__ A2,
                  const float* __restrict__ W3, const float* __restrict__ b3,
                  const float* __restrict__ A3,
                  const float* __restrict__ Wf, const float* __restrict__ bf,
                  float* __restrict__ out, int E) {
    extern __shared__ float sm[];
    float* sm_h1 = sm;                  // 8192 floats (swizzled k-major)
    float* sm_X  = sm + 8192;           // 4224 (Wc [64][64], then h2 [32][132])
    float* sm_w3 = sm + 8192 + 4224;    // 1024 ([W3|A3] [32][32])

    const int tid = threadIdx.x;
    const int e_base = blockIdx.x * TILE_E;
    const int warp = tid >> 5;
    const int lane = tid & 31;

    // ---- weight staging ----
    #pragma unroll
    for (int i = 0; i < 16; i++) {
        int idx = tid + i * 256;
        int k = idx >> 6, n = idx & 63;
        sm_X[k * 64 + n] = (n < 32) ? W2[k * 32 + n] : A2[k * 32 + (n - 32)];
    }
    #pragma unroll
    for (int i = 0; i < 4; i++) {
        int idx = tid + i * 256;
        int k = idx >> 5, n = idx & 31;
        sm_w3[k * 32 + n] = (n < 16) ? W3[k * 16 + n] : A3[k * 16 + (n - 16)];
    }

    // ---- Stage A: coalesced gather + layer1, 16 edges per warp ----
    {
        const int e0 = e_base + warp * 16;
        int myidx = 0;
        {
            int el = lane & 15;
            int eg = e0 + el;
            if (eg < E) myidx = (lane < 16) ? ei[eg] : ei[(size_t)E + eg];
            myidx = min(max(myidx, 0), MAX_NODES - 1);
        }
        const int l15 = lane & 15;
        const float4 b1v = *(const float4*)(b1 + 4 * l15);
        const int j0 = 4 * l15;
        const int xg = l15 & 7;

        #pragma unroll
        for (int p = 0; p < 8; p++) {
            const int srcA = __shfl_sync(0xffffffffu, myidx, 2 * p);
            const int dstA = __shfl_sync(0xffffffffu, myidx, 16 + 2 * p);
            const int srcB = __shfl_sync(0xffffffffu, myidx, 2 * p + 1);
            const int dstB = __shfl_sync(0xffffffffu, myidx, 17 + 2 * p);

            const float4 sA = *(const float4*)(g_P + (size_t)srcA * P_COLS + lane * 4);
            const float4 dA = *(const float4*)(g_P + (size_t)dstA * P_COLS + 128 + lane * 4);
            const float4 sB = *(const float4*)(g_P + (size_t)srcB * P_COLS + lane * 4);
            const float4 dB = *(const float4*)(g_P + (size_t)dstB * P_COLS + 128 + lane * 4);

            float4 wA, wB;
            wA.x = sA.x + dA.x; wA.y = sA.y + dA.y; wA.z = sA.z + dA.z; wA.w = sA.w + dA.w;
            wB.x = sB.x + dB.x; wB.y = sB.y + dB.y; wB.z = sB.z + dB.z; wB.w = sB.w + dB.w;

            const bool lo = (lane < 16);
            // single exchange: lo lanes send wB, receive wA's A-half
            float4 t, o;
            t.x = lo ? wB.x : wA.x;  t.y = lo ? wB.y : wA.y;
            t.z = lo ? wB.z : wA.z;  t.w = lo ? wB.w : wA.w;
            o.x = __shfl_xor_sync(0xffffffffu, t.x, 16);
            o.y = __shfl_xor_sync(0xffffffffu, t.y, 16);
            o.z = __shfl_xor_sync(0xffffffffu, t.z, 16);
            o.w = __shfl_xor_sync(0xffffffffu, t.w, 16);

            float4 w, a;
            w.x = lo ? wA.x : o.x;  a.x = lo ? o.x : wB.x;
            w.y = lo ? wA.y : o.y;  a.y = lo ? o.y : wB.y;
            w.z = lo ? wA.z : o.z;  a.z = lo ? o.z : wB.z;
            w.w = lo ? wA.w : o.w;  a.w = lo ? o.w : wB.w;

            float h0  = fmaxf(fmaxf(w.x + b1v.x, 0.f) + a.x, 0.f);
            float h1v = fmaxf(fmaxf(w.y + b1v.y, 0.f) + a.y, 0.f);
            float h2v = fmaxf(fmaxf(w.z + b1v.z, 0.f) + a.z, 0.f);
            float h3v = fmaxf(fmaxf(w.w + b1v.w, 0.f) + a.w, 0.f);

            const int e_loc = warp * 16 + 2 * p + (lo ? 0 : 1);
            const int base = j0 * H1_PITCH + ((((e_loc >> 2) ^ xg)) << 2) + (e_loc & 3);
            sm_h1[base]                = h0;
            sm_h1[base + H1_PITCH]     = h1v;
            sm_h1[base + 2 * H1_PITCH] = h2v;
            sm_h1[base + 3 * H1_PITCH] = h3v;
        }
    }
    __syncthreads();

    // ---- Stage B: layer2 GEMM, out[128][64] ([W2 cols | A2 cols]) ----
    const int tx = tid & 15;
    const int ty = tid >> 4;
    const int m0 = ty * 8;
    const int n0 = tx * 4;
    const int g0 = 2 * ty;
    const int g1 = 2 * ty + 1;

    ull acc[4][4];
    #pragma unroll
    for (int ip = 0; ip < 4; ip++)
        #pragma unroll
        for (int c = 0; c < 4; c++) acc[ip][c] = 0ull;

    // k grouped by xr = k>>2 (swizzle constant within group of 4)
    #pragma unroll
    for (int kb = 0; kb < 16; kb++) {
        const int xr = kb & 7;
        const float* pa0 = sm_h1 + kb * 4 * H1_PITCH + ((g0 ^ xr) << 2);
        const float* pa1 = sm_h1 + kb * 4 * H1_PITCH + ((g1 ^ xr) << 2);
        const float* pb  = sm_X + kb * 4 * 64 + n0;
        #pragma unroll
        for (int kk = 0; kk < 4; kk++) {
            const double2 A0 = *(const double2*)(pa0 + kk * H1_PITCH);
            const double2 A1 = *(const double2*)(pa1 + kk * H1_PITCH);
            const float4 b = *(const float4*)(pb + kk * 64);
            ull ar[4] = { dbits(A0.x), dbits(A0.y), dbits(A1.x), dbits(A1.y) };
            ull bd[4] = { pack2(b.x, b.x), pack2(b.y, b.y), pack2(b.z, b.z), pack2(b.w, b.w) };
            #pragma unroll
            for (int ip = 0; ip < 4; ip++)
                #pragma unroll
                for (int c = 0; c < 4; c++)
                    acc[ip][c] = fma2(ar[ip], bd[c], acc[ip][c]);
        }
    }
    __syncthreads();  // all Wc reads done before h2 overwrites sm_X

    // combine W/A halves: tx<8 holds W cols n0..n0+3; A part at lane+8
    #pragma unroll
    for (int ip = 0; ip < 4; ip++) {
        #pragma unroll
        for (int c = 0; c < 4; c++) {
            ull other = __shfl_down_sync(0xffffffffu, acc[ip][c], 8);
            if (tx < 8) {
                float wlo, whi, alo, ahi;
                unpack2(acc[ip][c], wlo, whi);
                unpack2(other, alo, ahi);
                float bb = __ldg(b2 + n0 + c);
                float v0 = fmaxf(fmaxf(wlo + bb, 0.f) + alo, 0.f);
                float v1 = fmaxf(fmaxf(whi + bb, 0.f) + ahi, 0.f);
                sm_X[(n0 + c) * H2_PITCH + m0 + 2 * ip]     = v0;
                sm_X[(n0 + c) * H2_PITCH + m0 + 2 * ip + 1] = v1;
            }
        }
    }
    __syncwarp();   // h2 producer/consumer is warp-local

    // ---- Stage C: layer3 GEMM out[128][32] ([W3 | A3]) + head ----
    const int n0c = tx * 2;
    ull acc3[4][2];
    #pragma unroll
    for (int ip = 0; ip < 4; ip++) { acc3[ip][0] = 0ull; acc3[ip][1] = 0ull; }

    #pragma unroll
    for (int kb = 0; kb < 8; kb++) {
        const float* pa0 = sm_X + kb * 4 * H2_PITCH + m0;
        const float* pb  = sm_w3 + kb * 4 * 32 + n0c;
        #pragma unroll
        for (int kk = 0; kk < 4; kk++) {
            const double2 A0 = *(const double2*)(pa0 + kk * H2_PITCH);
            const double2 A1 = *(const double2*)(pa0 + kk * H2_PITCH + 4);
            const float2 b = *(const float2*)(pb + kk * 32);
            ull ar[4] = { dbits(A0.x), dbits(A0.y), dbits(A1.x), dbits(A1.y) };
            ull bd0 = pack2(b.x, b.x);
            ull bd1 = pack2(b.y, b.y);
            #pragma unroll
            for (int ip = 0; ip < 4; ip++) {
                acc3[ip][0] = fma2(ar[ip], bd0, acc3[ip][0]);
                acc3[ip][1] = fma2(ar[ip], bd1, acc3[ip][1]);
            }
        }
    }

    float p[8];
    #pragma unroll
    for (int i = 0; i < 8; i++) p[i] = 0.f;

    #pragma unroll
    for (int ip = 0; ip < 4; ip++) {
        #pragma unroll
        for (int c = 0; c < 2; c++) {
            ull other = __shfl_down_sync(0xffffffffu, acc3[ip][c], 8);
            if (tx < 8) {
                float wlo, whi, alo, ahi;
                unpack2(acc3[ip][c], wlo, whi);
                unpack2(other, alo, ahi);
                int n = n0c + c;
                float bb = __ldg(b3 + n);
                float wf = __ldg(Wf + n);
                float h3lo = fmaxf(fmaxf(wlo + bb, 0.f) + alo, 0.f);
                float h3hi = fmaxf(fmaxf(whi + bb, 0.f) + ahi, 0.f);
                p[2 * ip]     += h3lo * wf;
                p[2 * ip + 1] += h3hi * wf;
            }
        }
    }

    #pragma unroll
    for (int o = 1; o < 8; o <<= 1) {
        #pragma unroll
        for (int i = 0; i < 8; i++)
            p[i] += __shfl_xor_sync(0xffffffffu, p[i], o);
    }

    if (tx == 0) {
        float bfv = __ldg(bf);
        #pragma unroll
        for (int i = 0; i < 8; i++) {
            int eg = e_base + m0 + i;
            if (eg < E) out[eg] = 1.f / (1.f + expf(-(p[i] + bfv)));
        }
    }
}

// ---------------------------------------------------------------------------
extern "C" void kernel_launch(void* const* d_in, const int* in_sizes, int n_in,
                              void* d_out, int out_size) {
    const float* x  = (const float*)d_in[0];
    const int*   ei = (const int*)d_in[1];
    const float* W1 = (const float*)d_in[2];
    const float* b1 = (const float*)d_in[3];
    const float* A1 = (const float*)d_in[4];
    const float* W2 = (const float*)d_in[5];
    const float* b2 = (const float*)d_in[6];
    const float* A2 = (const float*)d_in[7];
    const float* W3 = (const float*)d_in[8];
    const float* b3 = (const float*)d_in[9];
    const float* A3 = (const float*)d_in[10];
    const float* Wf = (const float*)d_in[11];
    const float* bf = (const float*)d_in[12];
    float* out = (float*)d_out;

    const int n_nodes = in_sizes[0] / F_DIM;
    const int E = in_sizes[1] / 2;

    const int pre_smem = (128 * XP + 128 * 64) * 4;     // 100352
    cudaFuncSetAttribute(precompute_kernel4, cudaFuncAttributeMaxDynamicSharedMemorySize, pre_smem);
    precompute_kernel4<<<(n_nodes + 127) / 128, 256, pre_smem>>>(x, W1, A1, n_nodes);

    const int smem_bytes = (8192 + 4224 + 1024) * 4;    // 53760
    cudaFuncSetAttribute(edge_kernel5, cudaFuncAttributeMaxDynamicSharedMemorySize, smem_bytes);
    const int nb = (E + TILE_E - 1) / TILE_E;
    edge_kernel5<<<nb, 256, smem_bytes>>>(ei, b1, W2, b2, A2, W3, b3, A3, Wf, bf, out, E);
}

// round 8
// speedup vs baseline: 1.1993x; 1.0037x over previous
#include <cuda_runtime.h>
#include <cuda_fp16.h>
#include <math.h>

#define MAX_NODES 100000
#define F_DIM 128
// g_P stored as fp16: [node][256 halves] = [PW_s(64)|PA_s(64)|PW_d(64)|PA_d(64)]
__device__ __half2 g_P[(size_t)MAX_NODES * 128];

// ---------------- packed f32x2 helpers (sm_103a FFMA2) ----------------
typedef unsigned long long ull;
__device__ __forceinline__ ull pack2(float x, float y) {
    ull r; asm("mov.b64 %0, {%1,%2};" : "=l"(r) : "f"(x), "f"(y)); return r;
}
__device__ __forceinline__ void unpack2(ull v, float& x, float& y) {
    asm("mov.b64 {%0,%1}, %2;" : "=f"(x), "=f"(y) : "l"(v));
}
__device__ __forceinline__ ull fma2(ull a, ull b, ull c) {
    ull d; asm("fma.rn.f32x2 %0, %1, %2, %3;" : "=l"(d) : "l"(a), "l"(b), "l"(c)); return d;
}
__device__ __forceinline__ ull dbits(double d) { return __double_as_longlong(d); }
__device__ __forceinline__ unsigned h2u(__half2 h) { return *(unsigned*)&h; }
__device__ __forceinline__ __half2 u2h(unsigned u) { return *(__half2*)&u; }

// ---------------------------------------------------------------------------
// Kernel 1: P[n,:] = x[n,:] @ [W1top | A1top | W1bot | A1bot], fp16 output.
// One block per 128-node tile; Xs loaded once; 4 quadrants sequential.
// ---------------------------------------------------------------------------
#define XP 132
__global__ __launch_bounds__(256, 2)
void precompute_kernel5(const float* __restrict__ x,
                        const float* __restrict__ W1,
                        const float* __restrict__ A1,
                        int n_nodes) {
    extern __shared__ float psm[];
    float* Xs = psm;                 // [k=128][m=128], pitch 132
    float* Bs = psm + 128 * XP;      // [k=128][n=64]

    const int tid = threadIdx.x;
    const int m0b = blockIdx.x * 128;
    const int tx = tid & 15;
    const int ty = tid >> 4;
    const int m0 = ty * 8;
    const int n0 = tx * 4;

    __half* gph = (__half*)g_P;

    #pragma unroll
    for (int t = 0; t < 64; t++) {
        int i = tid + t * 256;
        int m = i >> 7, k = i & 127;
        int gm = m0b + m;
        Xs[k * XP + m] = (gm < n_nodes) ? x[(size_t)gm * F_DIM + k] : 0.f;
    }

    for (int q = 0; q < 4; q++) {
        __syncthreads();
        const float* srcq = ((q & 1) ? A1 : W1) + (size_t)(q >> 1) * 128 * 64;
        #pragma unroll
        for (int t = 0; t < 32; t++) {
            int i = tid + t * 256;
            Bs[i] = srcq[i];
        }
        __syncthreads();

        ull acc[4][4];
        #pragma unroll
        for (int i = 0; i < 4; i++)
            #pragma unroll
            for (int j = 0; j < 4; j++) acc[i][j] = 0ull;

        #pragma unroll 32
        for (int kk = 0; kk < 128; kk++) {
            const double2 av0 = *(const double2*)(Xs + kk * XP + m0);
            const double2 av1 = *(const double2*)(Xs + kk * XP + m0 + 4);
            const float4  bv  = *(const float4*)(Bs + kk * 64 + n0);
            ull ar[4] = { dbits(av0.x), dbits(av0.y), dbits(av1.x), dbits(av1.y) };
            ull bd[4] = { pack2(bv.x, bv.x), pack2(bv.y, bv.y),
                          pack2(bv.z, bv.z), pack2(bv.w, bv.w) };
            #pragma unroll
            for (int i = 0; i < 4; i++)
                #pragma unroll
                for (int j = 0; j < 4; j++)
                    acc[i][j] = fma2(ar[i], bd[j], acc[i][j]);
        }

        #pragma unroll
        for (int i = 0; i < 4; i++) {
            float r0[4], r1[4];
            #pragma unroll
            for (int j = 0; j < 4; j++) unpack2(acc[i][j], r0[j], r1[j]);
            int gm0 = m0b + m0 + 2 * i;
            if (gm0 < n_nodes) {
                __half2 p0 = __float22half2_rn(make_float2(r0[0], r0[1]));
                __half2 p1 = __float22half2_rn(make_float2(r0[2], r0[3]));
                *(uint2*)(gph + (size_t)gm0 * 256 + q * 64 + n0) = make_uint2(h2u(p0), h2u(p1));
            }
            if (gm0 + 1 < n_nodes) {
                __half2 p0 = __float22half2_rn(make_float2(r1[0], r1[1]));
                __half2 p1 = __float22half2_rn(make_float2(r1[2], r1[3]));
                *(uint2*)(gph + (size_t)(gm0 + 1) * 256 + q * 64 + n0) = make_uint2(h2u(p0), h2u(p1));
            }
        }
    }
}

// ---------------------------------------------------------------------------
// Kernel 2 (v6): 128 edges/block, 256 threads.
// sm_h1 [64][132] with conflict-free swizzle:
//   phys(j,e) = j*132 + (((e>>2) ^ ((j>>3)&7))<<2) + (e&3)
//   (pitch 132 folds (j>>2)&1 into the bank base -> 32 distinct banks on store)
// Stage B: warp = 32m x (16 W-cols + 16 A-cols), B-read 1 wf/k.
// ---------------------------------------------------------------------------
#define TILE_E 128
#define H1P 132
#define H2P 132

__global__ __launch_bounds__(256, 4)
void edge_kernel6(const int* __restrict__ ei,
                  const float* __restrict__ b1,
                  const float* __restrict__ W2, const float* __restrict__ b2,
                  const float* __restrict__ A2,
                  const float* __restrict__ W3, const float* __restrict__ b3,
                  const float* __restrict__ A3,
                  const float* __restrict__ Wf, const float* __restrict__ bf,
                  float* __restrict__ out, int E) {
    extern __shared__ float sm[];
    float* sm_h1 = sm;                      // 64*132 = 8448
    float* sm_X  = sm + 8448;               // 4224 (Wc [64][64], then h2 [32][132])
    float* sm_w3 = sm + 8448 + 4224;        // 1024

    const int tid = threadIdx.x;
    const int e_base = blockIdx.x * TILE_E;
    const int warp = tid >> 5;
    const int lane = tid & 31;

    // ---- weight staging ----
    #pragma unroll
    for (int i = 0; i < 16; i++) {
        int idx = tid + i * 256;
        int k = idx >> 6, n = idx & 63;
        sm_X[k * 64 + n] = (n < 32) ? W2[k * 32 + n] : A2[k * 32 + (n - 32)];
    }
    #pragma unroll
    for (int i = 0; i < 4; i++) {
        int idx = tid + i * 256;
        int k = idx >> 5, n = idx & 31;
        sm_w3[k * 32 + n] = (n < 16) ? W3[k * 16 + n] : A3[k * 16 + (n - 16)];
    }

    // ---- Stage A: fp16 gather + layer1, 16 edges per warp ----
    {
        const int l15 = lane & 15;
        int idx = 0;
        {
            int eg = e_base + warp * 16 + l15;
            if (eg < E) idx = (lane < 16) ? ei[eg] : ei[(size_t)E + eg];
            idx = min(max(idx, 0), MAX_NODES - 1);
        }
        const float4 b1v = *(const float4*)(b1 + 4 * l15);
        const int xg = (l15 >> 1) & 7;
        const bool lo = (lane < 16);
        const __half2* gp = g_P;

        #pragma unroll
        for (int p = 0; p < 8; p++) {
            const int srcA = __shfl_sync(0xffffffffu, idx, 2 * p);
            const int dstA = __shfl_sync(0xffffffffu, idx, 16 + 2 * p);
            const int srcB = __shfl_sync(0xffffffffu, idx, 2 * p + 1);
            const int dstB = __shfl_sync(0xffffffffu, idx, 17 + 2 * p);

            // lane covers 4 halves (values 4*lane..4*lane+3 of the 128-value half-row)
            const uint2 sa = *(const uint2*)(gp + (size_t)srcA * 128 + lane * 2);
            const uint2 da = *(const uint2*)(gp + (size_t)dstA * 128 + 64 + lane * 2);
            const uint2 sb = *(const uint2*)(gp + (size_t)srcB * 128 + lane * 2);
            const uint2 db = *(const uint2*)(gp + (size_t)dstB * 128 + 64 + lane * 2);

            const unsigned wa0 = h2u(__hadd2(u2h(sa.x), u2h(da.x)));
            const unsigned wa1 = h2u(__hadd2(u2h(sa.y), u2h(da.y)));
            const unsigned wb0 = h2u(__hadd2(u2h(sb.x), u2h(db.x)));
            const unsigned wb1 = h2u(__hadd2(u2h(sb.y), u2h(db.y)));

            // single exchange (lo lanes send edge-B's W half, receive edge-A's A half)
            const unsigned t0 = lo ? wb0 : wa0;
            const unsigned t1 = lo ? wb1 : wa1;
            const unsigned o0 = __shfl_xor_sync(0xffffffffu, t0, 16);
            const unsigned o1 = __shfl_xor_sync(0xffffffffu, t1, 16);

            const float2 wf0 = __half22float2(u2h(lo ? wa0 : o0));
            const float2 wf1 = __half22float2(u2h(lo ? wa1 : o1));
            const float2 af0 = __half22float2(u2h(lo ? o0 : wb0));
            const float2 af1 = __half22float2(u2h(lo ? o1 : wb1));

            const float h0  = fmaxf(fmaxf(wf0.x + b1v.x, 0.f) + af0.x, 0.f);
            const float h1v = fmaxf(fmaxf(wf0.y + b1v.y, 0.f) + af0.y, 0.f);
            const float h2v = fmaxf(fmaxf(wf1.x + b1v.z, 0.f) + af1.x, 0.f);
            const float h3v = fmaxf(fmaxf(wf1.y + b1v.w, 0.f) + af1.y, 0.f);

            const int e_loc = warp * 16 + 2 * p + (lo ? 0 : 1);
            const int base = (4 * l15) * H1P + (((e_loc >> 2) ^ xg) << 2) + (e_loc & 3);
            sm_h1[base]           = h0;
            sm_h1[base + H1P]     = h1v;
            sm_h1[base + 2 * H1P] = h2v;
            sm_h1[base + 3 * H1P] = h3v;
        }
    }
    __syncthreads();

    // ---- Stage B: layer2 GEMM. warp = 32m x (16 W + 16 A cols) ----
    const int tx8 = lane & 7;
    const int tyw = (lane >> 3) & 3;
    const int mg  = warp & 3;
    const int ng  = warp >> 2;
    const int m0  = mg * 32 + tyw * 8;
    const int nW  = ng * 16 + (tx8 & 3) * 4;           // logical W/A column block
    const int n0  = ((tx8 >= 4) ? 32 : 0) + nW;        // column in Wc = [W2|A2]
    const int g0  = m0 >> 2;                           // even

    ull acc[4][4];
    #pragma unroll
    for (int ip = 0; ip < 4; ip++)
        #pragma unroll
        for (int c = 0; c < 4; c++) acc[ip][c] = 0ull;

    #pragma unroll
    for (int kb = 0; kb < 8; kb++) {                   // xr = (k>>3)&7 = kb
        const float* pa0 = sm_h1 + kb * 8 * H1P + ((g0 ^ kb) << 2);
        const float* pa1 = sm_h1 + kb * 8 * H1P + (((g0 + 1) ^ kb) << 2);
        const float* pb  = sm_X + kb * 8 * 64 + n0;
        #pragma unroll
        for (int kk = 0; kk < 8; kk++) {
            const double2 A0 = *(const double2*)(pa0 + kk * H1P);
            const double2 A1 = *(const double2*)(pa1 + kk * H1P);
            const float4 b = *(const float4*)(pb + kk * 64);
            ull ar[4] = { dbits(A0.x), dbits(A0.y), dbits(A1.x), dbits(A1.y) };
            ull bd[4] = { pack2(b.x, b.x), pack2(b.y, b.y), pack2(b.z, b.z), pack2(b.w, b.w) };
            #pragma unroll
            for (int ip = 0; ip < 4; ip++)
                #pragma unroll
                for (int c = 0; c < 4; c++)
                    acc[ip][c] = fma2(ar[ip], bd[c], acc[ip][c]);
        }
    }
    __syncthreads();  // all Wc reads done before h2 overwrites sm_X

    // combine: tx8<4 holds W part; A part at tx8+4 (same tyw)
    #pragma unroll
    for (int ip = 0; ip < 4; ip++) {
        #pragma unroll
        for (int c = 0; c < 4; c++) {
            ull other = __shfl_down_sync(0xffffffffu, acc[ip][c], 4);
            if (tx8 < 4) {
                float wlo, whi, alo, ahi;
                unpack2(acc[ip][c], wlo, whi);
                unpack2(other, alo, ahi);
                float bb = __ldg(b2 + nW + c);
                float v0 = fmaxf(fmaxf(wlo + bb, 0.f) + alo, 0.f);
                float v1 = fmaxf(fmaxf(whi + bb, 0.f) + ahi, 0.f);
                *(float2*)(sm_X + (nW + c) * H2P + m0 + 2 * ip) = make_float2(v0, v1);
            }
        }
    }
    __syncthreads();  // h2 consumed cross-warp in Stage C

    // ---- Stage C: layer3 GEMM out[128][32] ([W3|A3]) + head ----
    const int tx = tid & 15;
    const int ty = tid >> 4;
    const int m0c = ty * 8;
    const int n0c = tx * 2;
    ull acc3[4][2];
    #pragma unroll
    for (int ip = 0; ip < 4; ip++) { acc3[ip][0] = 0ull; acc3[ip][1] = 0ull; }

    #pragma unroll
    for (int kb = 0; kb < 8; kb++) {
        const float* pa0 = sm_X + kb * 4 * H2P + m0c;
        const float* pb  = sm_w3 + kb * 4 * 32 + n0c;
        #pragma unroll
        for (int kk = 0; kk < 4; kk++) {
            const double2 A0 = *(const double2*)(pa0 + kk * H2P);
            const double2 A1 = *(const double2*)(pa0 + kk * H2P + 4);
            const float2 b = *(const float2*)(pb + kk * 32);
            ull ar[4] = { dbits(A0.x), dbits(A0.y), dbits(A1.x), dbits(A1.y) };
            ull bd0 = pack2(b.x, b.x);
            ull bd1 = pack2(b.y, b.y);
            #pragma unroll
            for (int ip = 0; ip < 4; ip++) {
                acc3[ip][0] = fma2(ar[ip], bd0, acc3[ip][0]);
                acc3[ip][1] = fma2(ar[ip], bd1, acc3[ip][1]);
            }
        }
    }

    float p[8];
    #pragma unroll
    for (int i = 0; i < 8; i++) p[i] = 0.f;

    #pragma unroll
    for (int ip = 0; ip < 4; ip++) {
        #pragma unroll
        for (int c = 0; c < 2; c++) {
            ull other = __shfl_down_sync(0xffffffffu, acc3[ip][c], 8);
            if (tx < 8) {
                float wlo, whi, alo, ahi;
                unpack2(acc3[ip][c], wlo, whi);
                unpack2(other, alo, ahi);
                int n = n0c + c;
                float bb = __ldg(b3 + n);
                float wf = __ldg(Wf + n);
                float h3lo = fmaxf(fmaxf(wlo + bb, 0.f) + alo, 0.f);
                float h3hi = fmaxf(fmaxf(whi + bb, 0.f) + ahi, 0.f);
                p[2 * ip]     += h3lo * wf;
                p[2 * ip + 1] += h3hi * wf;
            }
        }
    }

    #pragma unroll
    for (int o = 1; o < 8; o <<= 1) {
        #pragma unroll
        for (int i = 0; i < 8; i++)
            p[i] += __shfl_xor_sync(0xffffffffu, p[i], o);
    }

    if (tx == 0) {
        float bfv = __ldg(bf);
        #pragma unroll
        for (int i = 0; i < 8; i++) {
            int eg = e_base + m0c + i;
            if (eg < E) out[eg] = 1.f / (1.f + expf(-(p[i] + bfv)));
        }
    }
}

// ---------------------------------------------------------------------------
extern "C" void kernel_launch(void* const* d_in, const int* in_sizes, int n_in,
                              void* d_out, int out_size) {
    const float* x  = (const float*)d_in[0];
    const int*   ei = (const int*)d_in[1];
    const float* W1 = (const float*)d_in[2];
    const float* b1 = (const float*)d_in[3];
    const float* A1 = (const float*)d_in[4];
    const float* W2 = (const float*)d_in[5];
    const float* b2 = (const float*)d_in[6];
    const float* A2 = (const float*)d_in[7];
    const float* W3 = (const float*)d_in[8];
    const float* b3 = (const float*)d_in[9];
    const float* A3 = (const float*)d_in[10];
    const float* Wf = (const float*)d_in[11];
    const float* bf = (const float*)d_in[12];
    float* out = (float*)d_out;

    const int n_nodes = in_sizes[0] / F_DIM;
    const int E = in_sizes[1] / 2;

    const int pre_smem = (128 * XP + 128 * 64) * 4;     // 100352
    cudaFuncSetAttribute(precompute_kernel5, cudaFuncAttributeMaxDynamicSharedMemorySize, pre_smem);
    precompute_kernel5<<<(n_nodes + 127) / 128, 256, pre_smem>>>(x, W1, A1, n_nodes);

    const int smem_bytes = (8448 + 4224 + 1024) * 4;    // 54784
    cudaFuncSetAttribute(edge_kernel6, cudaFuncAttributeMaxDynamicSharedMemorySize, smem_bytes);
    const int nb = (E + TILE_E - 1) / TILE_E;
    edge_kernel6<<<nb, 256, smem_bytes>>>(ei, b1, W2, b2, A2, W3, b3, A3, Wf, bf, out, E);
}

// round 9
// speedup vs baseline: 2.0253x; 1.6888x over previous
#include <cuda_runtime.h>
#include <cuda_fp16.h>
#include <math.h>

#define MAX_NODES 100000
#define F_DIM 128
#define P_COLS 256   // fp32: [PW_s(64)|PA_s(64)|PW_d(64)|PA_d(64)]

__device__ float g_P[(size_t)MAX_NODES * P_COLS];

// ---------------- packed f32x2 helpers (sm_103a FFMA2) ----------------
typedef unsigned long long ull;
__device__ __forceinline__ ull pack2(float x, float y) {
    ull r; asm("mov.b64 %0, {%1,%2};" : "=l"(r) : "f"(x), "f"(y)); return r;
}
__device__ __forceinline__ void unpack2(ull v, float& x, float& y) {
    asm("mov.b64 {%0,%1}, %2;" : "=f"(x), "=f"(y) : "l"(v));
}
__device__ __forceinline__ ull fma2(ull a, ull b, ull c) {
    ull d; asm("fma.rn.f32x2 %0, %1, %2, %3;" : "=l"(d) : "l"(a), "l"(b), "l"(c)); return d;
}
__device__ __forceinline__ ull dbits(double d) { return __double_as_longlong(d); }

// ---------------- mma / ldmatrix helpers ----------------
__device__ __forceinline__ unsigned sm_u32(const void* p) {
    unsigned a;
    asm("{ .reg .u64 t; cvta.to.shared.u64 t, %1; cvt.u32.u64 %0, t; }" : "=r"(a) : "l"(p));
    return a;
}
__device__ __forceinline__ void ldmat4(unsigned& r0, unsigned& r1, unsigned& r2, unsigned& r3,
                                       unsigned addr) {
    asm volatile("ldmatrix.sync.aligned.m8n8.x4.shared.b16 {%0,%1,%2,%3}, [%4];"
                 : "=r"(r0), "=r"(r1), "=r"(r2), "=r"(r3) : "r"(addr));
}
__device__ __forceinline__ void stmat4(unsigned addr, unsigned r0, unsigned r1,
                                       unsigned r2, unsigned r3) {
    asm volatile("stmatrix.sync.aligned.m8n8.x4.shared.b16 [%0], {%1,%2,%3,%4};"
                 :: "r"(addr), "r"(r0), "r"(r1), "r"(r2), "r"(r3) : "memory");
}
__device__ __forceinline__ void mma16816(float* c, unsigned a0, unsigned a1, unsigned a2,
                                         unsigned a3, unsigned b0, unsigned b1) {
    asm volatile(
        "mma.sync.aligned.m16n8k16.row.col.f32.f16.f16.f32 "
        "{%0,%1,%2,%3}, {%4,%5,%6,%7}, {%8,%9}, {%0,%1,%2,%3};"
        : "+f"(c[0]), "+f"(c[1]), "+f"(c[2]), "+f"(c[3])
        : "r"(a0), "r"(a1), "r"(a2), "r"(a3), "r"(b0), "r"(b1));
}
__device__ __forceinline__ unsigned h2u(__half2 h) { return *(unsigned*)&h; }

// ---------------------------------------------------------------------------
// Kernel 1 (proven R7): P[n,:] = x[n,:] @ [W1top|A1top|W1bot|A1bot], fp32 out.
// ---------------------------------------------------------------------------
#define XP 132
__global__ __launch_bounds__(256, 2)
void precompute_kernel4(const float* __restrict__ x,
                        const float* __restrict__ W1,
                        const float* __restrict__ A1,
                        int n_nodes) {
    extern __shared__ float psm[];
    float* Xs = psm;                 // [k=128][m=128], pitch 132
    float* Bs = psm + 128 * XP;      // [k=128][n=64]

    const int tid = threadIdx.x;
    const int m0b = blockIdx.x * 128;
    const int tx = tid & 15;
    const int ty = tid >> 4;
    const int m0 = ty * 8;
    const int n0 = tx * 4;

    #pragma unroll
    for (int t = 0; t < 64; t++) {
        int i = tid + t * 256;
        int m = i >> 7, k = i & 127;
        int gm = m0b + m;
        Xs[k * XP + m] = (gm < n_nodes) ? x[(size_t)gm * F_DIM + k] : 0.f;
    }

    for (int q = 0; q < 4; q++) {
        __syncthreads();
        const float* srcq = ((q & 1) ? A1 : W1) + (size_t)(q >> 1) * 128 * 64;
        #pragma unroll
        for (int t = 0; t < 32; t++) {
            int i = tid + t * 256;
            Bs[i] = srcq[i];
        }
        __syncthreads();

        ull acc[4][4];
        #pragma unroll
        for (int i = 0; i < 4; i++)
            #pragma unroll
            for (int j = 0; j < 4; j++) acc[i][j] = 0ull;

        #pragma unroll 32
        for (int kk = 0; kk < 128; kk++) {
            const double2 av0 = *(const double2*)(Xs + kk * XP + m0);
            const double2 av1 = *(const double2*)(Xs + kk * XP + m0 + 4);
            const float4  bv  = *(const float4*)(Bs + kk * 64 + n0);
            ull ar[4] = { dbits(av0.x), dbits(av0.y), dbits(av1.x), dbits(av1.y) };
            ull bd[4] = { pack2(bv.x, bv.x), pack2(bv.y, bv.y),
                          pack2(bv.z, bv.z), pack2(bv.w, bv.w) };
            #pragma unroll
            for (int i = 0; i < 4; i++)
                #pragma unroll
                for (int j = 0; j < 4; j++)
                    acc[i][j] = fma2(ar[i], bd[j], acc[i][j]);
        }

        #pragma unroll
        for (int i = 0; i < 4; i++) {
            float r0[4], r1[4];
            #pragma unroll
            for (int j = 0; j < 4; j++) unpack2(acc[i][j], r0[j], r1[j]);
            int gm0 = m0b + m0 + 2 * i;
            if (gm0 < n_nodes)
                *(float4*)(&g_P[(size_t)gm0 * P_COLS + q * 64 + n0]) =
                    make_float4(r0[0], r0[1], r0[2], r0[3]);
            if (gm0 + 1 < n_nodes)
                *(float4*)(&g_P[(size_t)(gm0 + 1) * P_COLS + q * 64 + n0]) =
                    make_float4(r1[0], r1[1], r1[2], r1[3]);
        }
    }
}

// ---------------------------------------------------------------------------
// Kernel 2 (v7, HMMA): 128 edges/block, 256 threads, warp owns 16 edges
// end-to-end (gather -> h1 -> mma layer2 -> mma layer3 -> head). fp16 h1/h2 &
// weights, fp32 accum via mma.sync.m16n8k16.
// smem (halves): h1s[128][72] | h2s[128][40] | Wc[64][72] | W3c[32][40]
// ---------------------------------------------------------------------------
#define TILE_E 128
#define H1PH 72    // h1 pitch in halves (144B: ldmatrix conflict-free)
#define H2PH 40    // h2 pitch in halves (80B: conflict-free)

__global__ __launch_bounds__(256, 4)
void edge_kernel7(const int* __restrict__ ei,
                  const float* __restrict__ b1,
                  const float* __restrict__ W2, const float* __restrict__ b2,
                  const float* __restrict__ A2,
                  const float* __restrict__ W3, const float* __restrict__ b3,
                  const float* __restrict__ A3,
                  const float* __restrict__ Wf, const float* __restrict__ bf,
                  float* __restrict__ out, int E) {
    extern __shared__ __half hs[];
    __half* h1s = hs;                           // 128*72 = 9216
    __half* h2s = hs + 9216;                    // 128*40 = 5120
    __half* Wc  = hs + 9216 + 5120;             // 64*72  = 4608  [n][k]
    __half* W3c = hs + 9216 + 5120 + 4608;      // 32*40  = 1280  [n][k]

    const int tid = threadIdx.x;
    const int e_base = blockIdx.x * TILE_E;
    const int warp = tid >> 5;
    const int lane = tid & 31;
    const int lq = lane & 3;          // quad index
    const int lr = lane >> 2;         // row-in-8 index
    const int m0 = warp * 16;

    // ---- weight staging (coalesced LDG, transposed STS to n-major fp16) ----
    #pragma unroll
    for (int t = 0; t < 8; t++) {
        int i = tid + t * 256;           // 0..2047
        int k = i >> 5, n = i & 31;
        Wc[n * H1PH + k]        = __float2half(W2[i]);
        Wc[(32 + n) * H1PH + k] = __float2half(A2[i]);
    }
    #pragma unroll
    for (int t = 0; t < 2; t++) {
        int i = tid + t * 256;           // 0..511
        int k = i >> 4, n = i & 15;
        W3c[n * H2PH + k]        = __float2half(W3[i]);
        W3c[(16 + n) * H2PH + k] = __float2half(A3[i]);
    }

    // ---- Stage A: fp32 gather + layer1 (fp32) -> fp16 h1s, 16 edges/warp ----
    {
        const int l15 = lane & 15;
        int idx = 0;
        {
            int eg = e_base + warp * 16 + l15;
            if (eg < E) idx = (lane < 16) ? ei[eg] : ei[(size_t)E + eg];
            idx = min(max(idx, 0), MAX_NODES - 1);
        }
        const float4 b1v = *(const float4*)(b1 + 4 * l15);
        const bool lo = (lane < 16);

        #pragma unroll
        for (int p = 0; p < 8; p++) {
            const int srcA = __shfl_sync(0xffffffffu, idx, 2 * p);
            const int dstA = __shfl_sync(0xffffffffu, idx, 16 + 2 * p);
            const int srcB = __shfl_sync(0xffffffffu, idx, 2 * p + 1);
            const int dstB = __shfl_sync(0xffffffffu, idx, 17 + 2 * p);

            const float4 sA = *(const float4*)(g_P + (size_t)srcA * P_COLS + lane * 4);
            const float4 dA = *(const float4*)(g_P + (size_t)dstA * P_COLS + 128 + lane * 4);
            const float4 sB = *(const float4*)(g_P + (size_t)srcB * P_COLS + lane * 4);
            const float4 dB = *(const float4*)(g_P + (size_t)dstB * P_COLS + 128 + lane * 4);

            float4 wA, wB;
            wA.x = sA.x + dA.x; wA.y = sA.y + dA.y; wA.z = sA.z + dA.z; wA.w = sA.w + dA.w;
            wB.x = sB.x + dB.x; wB.y = sB.y + dB.y; wB.z = sB.z + dB.z; wB.w = sB.w + dB.w;

            float4 t, o;
            t.x = lo ? wB.x : wA.x;  t.y = lo ? wB.y : wA.y;
            t.z = lo ? wB.z : wA.z;  t.w = lo ? wB.w : wA.w;
            o.x = __shfl_xor_sync(0xffffffffu, t.x, 16);
            o.y = __shfl_xor_sync(0xffffffffu, t.y, 16);
            o.z = __shfl_xor_sync(0xffffffffu, t.z, 16);
            o.w = __shfl_xor_sync(0xffffffffu, t.w, 16);

            float4 w, a;
            w.x = lo ? wA.x : o.x;  a.x = lo ? o.x : wB.x;
            w.y = lo ? wA.y : o.y;  a.y = lo ? o.y : wB.y;
            w.z = lo ? wA.z : o.z;  a.z = lo ? o.z : wB.z;
            w.w = lo ? wA.w : o.w;  a.w = lo ? o.w : wB.w;

            const float h0  = fmaxf(fmaxf(w.x + b1v.x, 0.f) + a.x, 0.f);
            const float h1v = fmaxf(fmaxf(w.y + b1v.y, 0.f) + a.y, 0.f);
            const float h2v = fmaxf(fmaxf(w.z + b1v.z, 0.f) + a.z, 0.f);
            const float h3v = fmaxf(fmaxf(w.w + b1v.w, 0.f) + a.w, 0.f);

            const int e_loc = warp * 16 + 2 * p + (lo ? 0 : 1);
            __half2 q01 = __floats2half2_rn(h0, h1v);
            __half2 q23 = __floats2half2_rn(h2v, h3v);
            *(uint2*)(h1s + e_loc * H1PH + 4 * l15) = make_uint2(h2u(q01), h2u(q23));
        }
    }
    __syncthreads();   // Wc/W3c (cross-warp) + h1s ready

    // ---- Stage B: layer2 via mma. Warp: [16m] x [64n = W2|A2] x [64k] ----
    const unsigned h1_a = sm_u32(h1s) +
        ((m0 + (lane & 15)) * H1PH + ((lane >> 4) << 3)) * 2;
    float acc[8][4];
    #pragma unroll
    for (int nb = 0; nb < 8; nb++)
        #pragma unroll
        for (int c = 0; c < 4; c++) acc[nb][c] = 0.f;

    #pragma unroll
    for (int kb = 0; kb < 4; kb++) {
        unsigned a0, a1, a2, a3;
        ldmat4(a0, a1, a2, a3, h1_a + kb * 32);
        #pragma unroll
        for (int nb = 0; nb < 8; nb++) {
            const __half* bp = Wc + (nb * 8 + lr) * H1PH + kb * 16 + 2 * lq;
            unsigned b0 = *(const unsigned*)bp;
            unsigned b1r = *(const unsigned*)(bp + 8);
            mma16816(acc[nb], a0, a1, a2, a3, b0, b1r);
        }
    }

    // combine W/A, relu, write h2 (fp16) via stmatrix — all warp-local
    {
        unsigned regs[8];
        #pragma unroll
        for (int j = 0; j < 4; j++) {
            const float2 bb = __ldg((const float2*)(b2 + 8 * j + 2 * lq));
            float v0 = fmaxf(fmaxf(acc[j][0] + bb.x, 0.f) + acc[j + 4][0], 0.f);
            float v1 = fmaxf(fmaxf(acc[j][1] + bb.y, 0.f) + acc[j + 4][1], 0.f);
            float v2 = fmaxf(fmaxf(acc[j][2] + bb.x, 0.f) + acc[j + 4][2], 0.f);
            float v3 = fmaxf(fmaxf(acc[j][3] + bb.y, 0.f) + acc[j + 4][3], 0.f);
            regs[2 * j]     = h2u(__floats2half2_rn(v0, v1));   // rows r
            regs[2 * j + 1] = h2u(__floats2half2_rn(v2, v3));   // rows r+8
        }
        const unsigned h2_a = sm_u32(h2s) +
            ((m0 + (lane & 15)) * H2PH + ((lane >> 4) << 3)) * 2;
        stmat4(h2_a,      regs[0], regs[1], regs[2], regs[3]);   // cols 0-15
        stmat4(h2_a + 32, regs[4], regs[5], regs[6], regs[7]);   // cols 16-31
    }
    __syncwarp();

    // ---- Stage C: layer3 via mma. [16m] x [32n = W3|A3] x [32k] + head ----
    const unsigned h2_ra = sm_u32(h2s) +
        ((m0 + (lane & 15)) * H2PH + ((lane >> 4) << 3)) * 2;
    float acc3[4][4];
    #pragma unroll
    for (int nb = 0; nb < 4; nb++)
        #pragma unroll
        for (int c = 0; c < 4; c++) acc3[nb][c] = 0.f;

    #pragma unroll
    for (int kb = 0; kb < 2; kb++) {
        unsigned a0, a1, a2, a3;
        ldmat4(a0, a1, a2, a3, h2_ra + kb * 32);
        #pragma unroll
        for (int nb = 0; nb < 4; nb++) {
            const __half* bp = W3c + (nb * 8 + lr) * H2PH + kb * 16 + 2 * lq;
            unsigned b0 = *(const unsigned*)bp;
            unsigned b1r = *(const unsigned*)(bp + 8);
            mma16816(acc3[nb], a0, a1, a2, a3, b0, b1r);
        }
    }

    // head: h3 = relu(relu(W+b3)+A) for n'' = 8j'+2q+{0,1}, j'=0,1; dot with Wf
    float pr = 0.f, pr8 = 0.f;
    #pragma unroll
    for (int j = 0; j < 2; j++) {
        const float2 bb = __ldg((const float2*)(b3 + 8 * j + 2 * lq));
        const float2 wf = __ldg((const float2*)(Wf + 8 * j + 2 * lq));
        float v0 = fmaxf(fmaxf(acc3[j][0] + bb.x, 0.f) + acc3[j + 2][0], 0.f);
        float v1 = fmaxf(fmaxf(acc3[j][1] + bb.y, 0.f) + acc3[j + 2][1], 0.f);
        float v2 = fmaxf(fmaxf(acc3[j][2] + bb.x, 0.f) + acc3[j + 2][2], 0.f);
        float v3 = fmaxf(fmaxf(acc3[j][3] + bb.y, 0.f) + acc3[j + 2][3], 0.f);
        pr  += v0 * wf.x + v1 * wf.y;
        pr8 += v2 * wf.x + v3 * wf.y;
    }
    pr  += __shfl_xor_sync(0xffffffffu, pr, 1);
    pr  += __shfl_xor_sync(0xffffffffu, pr, 2);
    pr8 += __shfl_xor_sync(0xffffffffu, pr8, 1);
    pr8 += __shfl_xor_sync(0xffffffffu, pr8, 2);

    if (lq == 0) {
        const float bfv = __ldg(bf);
        int eg = e_base + m0 + lr;
        if (eg < E)     out[eg]     = 1.f / (1.f + expf(-(pr + bfv)));
        if (eg + 8 < E) out[eg + 8] = 1.f / (1.f + expf(-(pr8 + bfv)));
    }
}

// ---------------------------------------------------------------------------
extern "C" void kernel_launch(void* const* d_in, const int* in_sizes, int n_in,
                              void* d_out, int out_size) {
    const float* x  = (const float*)d_in[0];
    const int*   ei = (const int*)d_in[1];
    const float* W1 = (const float*)d_in[2];
    const float* b1 = (const float*)d_in[3];
    const float* A1 = (const float*)d_in[4];
    const float* W2 = (const float*)d_in[5];
    const float* b2 = (const float*)d_in[6];
    const float* A2 = (const float*)d_in[7];
    const float* W3 = (const float*)d_in[8];
    const float* b3 = (const float*)d_in[9];
    const float* A3 = (const float*)d_in[10];
    const float* Wf = (const float*)d_in[11];
    const float* bf = (const float*)d_in[12];
    float* out = (float*)d_out;

    const int n_nodes = in_sizes[0] / F_DIM;
    const int E = in_sizes[1] / 2;

    const int pre_smem = (128 * XP + 128 * 64) * 4;     // 100352
    cudaFuncSetAttribute(precompute_kernel4, cudaFuncAttributeMaxDynamicSharedMemorySize, pre_smem);
    precompute_kernel4<<<(n_nodes + 127) / 128, 256, pre_smem>>>(x, W1, A1, n_nodes);

    const int smem_bytes = (9216 + 5120 + 4608 + 1280) * 2;   // 40448
    cudaFuncSetAttribute(edge_kernel7, cudaFuncAttributeMaxDynamicSharedMemorySize, smem_bytes);
    const int nb = (E + TILE_E - 1) / TILE_E;
    edge_kernel7<<<nb, 256, smem_bytes>>>(ei, b1, W2, b2, A2, W3, b3, A3, Wf, bf, out, E);
}

// round 10
// speedup vs baseline: 2.7050x; 1.3356x over previous
#include <cuda_runtime.h>
#include <cuda_fp16.h>
#include <math.h>

#define MAX_NODES 100000
#define F_DIM 128
#define P_COLS 256   // fp32: [PW_s(64)|PA_s(64)|PW_d(64)|PA_d(64)]

__device__ float g_P[(size_t)MAX_NODES * P_COLS];

// ---------------- mma / ldmatrix helpers ----------------
__device__ __forceinline__ unsigned sm_u32(const void* p) {
    unsigned a;
    asm("{ .reg .u64 t; cvta.to.shared.u64 t, %1; cvt.u32.u64 %0, t; }" : "=r"(a) : "l"(p));
    return a;
}
__device__ __forceinline__ void ldmat4(unsigned& r0, unsigned& r1, unsigned& r2, unsigned& r3,
                                       unsigned addr) {
    asm volatile("ldmatrix.sync.aligned.m8n8.x4.shared.b16 {%0,%1,%2,%3}, [%4];"
                 : "=r"(r0), "=r"(r1), "=r"(r2), "=r"(r3) : "r"(addr));
}
__device__ __forceinline__ void ldmat4t(unsigned& r0, unsigned& r1, unsigned& r2, unsigned& r3,
                                        unsigned addr) {
    asm volatile("ldmatrix.sync.aligned.m8n8.x4.trans.shared.b16 {%0,%1,%2,%3}, [%4];"
                 : "=r"(r0), "=r"(r1), "=r"(r2), "=r"(r3) : "r"(addr));
}
__device__ __forceinline__ void stmat4(unsigned addr, unsigned r0, unsigned r1,
                                       unsigned r2, unsigned r3) {
    asm volatile("stmatrix.sync.aligned.m8n8.x4.shared.b16 [%0], {%1,%2,%3,%4};"
                 :: "r"(addr), "r"(r0), "r"(r1), "r"(r2), "r"(r3) : "memory");
}
__device__ __forceinline__ void mma16816(float* c, unsigned a0, unsigned a1, unsigned a2,
                                         unsigned a3, unsigned b0, unsigned b1) {
    asm volatile(
        "mma.sync.aligned.m16n8k16.row.col.f32.f16.f16.f32 "
        "{%0,%1,%2,%3}, {%4,%5,%6,%7}, {%8,%9}, {%0,%1,%2,%3};"
        : "+f"(c[0]), "+f"(c[1]), "+f"(c[2]), "+f"(c[3])
        : "r"(a0), "r"(a1), "r"(a2), "r"(a3), "r"(b0), "r"(b1));
}
__device__ __forceinline__ unsigned h2u(__half2 h) { return *(unsigned*)&h; }

// split a float4 into fp16 hi and lo half4s (as uint2 each)
__device__ __forceinline__ void split4(float4 v, uint2& hi, uint2& lo) {
    __half hx = __float2half_rn(v.x), hy = __float2half_rn(v.y);
    __half hz = __float2half_rn(v.z), hw = __float2half_rn(v.w);
    float lx = v.x - __half2float(hx), ly = v.y - __half2float(hy);
    float lz = v.z - __half2float(hz), lw = v.w - __half2float(hw);
    hi.x = h2u(__halves2half2(hx, hy));
    hi.y = h2u(__halves2half2(hz, hw));
    lo.x = h2u(__floats2half2_rn(lx, ly));
    lo.y = h2u(__floats2half2_rn(lz, lw));
}

// ---------------------------------------------------------------------------
// Kernel 1 (v6, HMMA split-fp16): P[n,:] = x[n,:] @ [W1top|A1top|W1bot|A1bot]
// fp32-accurate via 3-term split: xh@Wh + xh@Wl + xl@Wh.
// Block: 128 nodes, 256 threads (8 warps, warp = 16 m-rows).
// smem (halves): Ah[128][136] Al[128][136] Bh[128][72] Bl[128][72] = 106496 B
// B kept in natural [k][n] layout; B-fragments via ldmatrix.x4.trans.
// ---------------------------------------------------------------------------
#define APH 136
#define BPH 72
__global__ __launch_bounds__(256, 2)
void precompute_hmma(const float* __restrict__ x,
                     const float* __restrict__ W1,
                     const float* __restrict__ A1,
                     int n_nodes) {
    extern __shared__ __half ps[];
    __half* Ah = ps;                         // 128*136 = 17408
    __half* Al = ps + 17408;
    __half* Bh = ps + 2 * 17408;             // 128*72 = 9216
    __half* Bl = Bh + 9216;

    const int tid = threadIdx.x;
    const int m0b = blockIdx.x * 128;
    const int warp = tid >> 5;
    const int lane = tid & 31;
    const int lq = lane & 3;
    const int lr = lane >> 2;
    const int m0 = warp * 16;

    // ---- stage A = x tile, hi/lo split, [m][k] pitch 136 ----
    #pragma unroll
    for (int t = 0; t < 16; t++) {
        int i4 = tid + t * 256;               // 0..4095
        int m = i4 >> 5, k4 = i4 & 31;
        int gm = m0b + m;
        float4 v = (gm < n_nodes) ? *(const float4*)(x + (size_t)gm * F_DIM + k4 * 4)
                                  : make_float4(0.f, 0.f, 0.f, 0.f);
        uint2 hi, lo;
        split4(v, hi, lo);
        *(uint2*)(Ah + m * APH + k4 * 4) = hi;
        *(uint2*)(Al + m * APH + k4 * 4) = lo;
    }

    // ldmatrix lane addresses
    const unsigned a_hi = sm_u32(Ah) + ((m0 + (lane & 15)) * APH + ((lane >> 4) << 3)) * 2;
    const unsigned a_lo = sm_u32(Al) + ((m0 + (lane & 15)) * APH + ((lane >> 4) << 3)) * 2;
    const int bk  = (lane >> 3) & 1;          // k+8 select
    const int bn8 = (lane >> 4) & 1;          // n+8 select
    const int br  = lane & 7;
    const unsigned bh_base = sm_u32(Bh);
    const unsigned bl_base = sm_u32(Bl);

    for (int q = 0; q < 4; q++) {
        __syncthreads();   // q=0: A ready; q>0: prior B reads done
        // quadrant q: q0=W1[0:128], q1=A1[0:128], q2=W1[128:], q3=A1[128:]
        const float* srcq = ((q & 1) ? A1 : W1) + (size_t)(q >> 1) * 128 * 64;
        #pragma unroll
        for (int t = 0; t < 8; t++) {
            int i4 = tid + t * 256;           // 0..2047
            int k = i4 >> 4, n4 = i4 & 15;
            float4 v = *(const float4*)(srcq + k * 64 + n4 * 4);
            uint2 hi, lo;
            split4(v, hi, lo);
            *(uint2*)(Bh + k * BPH + n4 * 4) = hi;
            *(uint2*)(Bl + k * BPH + n4 * 4) = lo;
        }
        __syncthreads();

        float acc[8][4];
        #pragma unroll
        for (int nb = 0; nb < 8; nb++)
            #pragma unroll
            for (int c = 0; c < 4; c++) acc[nb][c] = 0.f;

        #pragma unroll
        for (int kb = 0; kb < 8; kb++) {
            unsigned ah0, ah1, ah2, ah3, al0, al1, al2, al3;
            ldmat4(ah0, ah1, ah2, ah3, a_hi + kb * 32);
            ldmat4(al0, al1, al2, al3, a_lo + kb * 32);
            #pragma unroll
            for (int nb2 = 0; nb2 < 4; nb2++) {
                const unsigned off =
                    ((kb * 16 + bk * 8 + br) * BPH + nb2 * 16 + bn8 * 8) * 2;
                unsigned bh0, bh1, bh2, bh3, bl0, bl1, bl2, bl3;
                ldmat4t(bh0, bh1, bh2, bh3, bh_base + off);
                ldmat4t(bl0, bl1, bl2, bl3, bl_base + off);
                mma16816(acc[2 * nb2],     ah0, ah1, ah2, ah3, bh0, bh1);
                mma16816(acc[2 * nb2],     ah0, ah1, ah2, ah3, bl0, bl1);
                mma16816(acc[2 * nb2],     al0, al1, al2, al3, bh0, bh1);
                mma16816(acc[2 * nb2 + 1], ah0, ah1, ah2, ah3, bh2, bh3);
                mma16816(acc[2 * nb2 + 1], ah0, ah1, ah2, ah3, bl2, bl3);
                mma16816(acc[2 * nb2 + 1], al0, al1, al2, al3, bh2, bh3);
            }
        }

        // epilogue: thread owns rows (m0+lr, m0+lr+8), cols nb*8 + 2lq..+1
        const int gm = m0b + m0 + lr;
        #pragma unroll
        for (int nb = 0; nb < 8; nb++) {
            const int n = q * 64 + nb * 8 + 2 * lq;
            if (gm < n_nodes)
                *(float2*)(g_P + (size_t)gm * P_COLS + n) = make_float2(acc[nb][0], acc[nb][1]);
            if (gm + 8 < n_nodes)
                *(float2*)(g_P + (size_t)(gm + 8) * P_COLS + n) = make_float2(acc[nb][2], acc[nb][3]);
        }
    }
}

// ---------------------------------------------------------------------------
// Kernel 2 (unchanged R9 HMMA edge kernel): 128 edges/block, warp owns 16
// edges end-to-end (gather -> h1 -> mma layer2 -> mma layer3 -> head).
// ---------------------------------------------------------------------------
#define TILE_E 128
#define H1PH 72
#define H2PH 40

__global__ __launch_bounds__(256, 4)
void edge_kernel7(const int* __restrict__ ei,
                  const float* __restrict__ b1,
                  const float* __restrict__ W2, const float* __restrict__ b2,
                  const float* __restrict__ A2,
                  const float* __restrict__ W3, const float* __restrict__ b3,
                  const float* __restrict__ A3,
                  const float* __restrict__ Wf, const float* __restrict__ bf,
                  float* __restrict__ out, int E) {
    extern __shared__ __half hs[];
    __half* h1s = hs;                           // 128*72 = 9216
    __half* h2s = hs + 9216;                    // 128*40 = 5120
    __half* Wc  = hs + 9216 + 5120;             // 64*72  = 4608  [n][k]
    __half* W3c = hs + 9216 + 5120 + 4608;      // 32*40  = 1280  [n][k]

    const int tid = threadIdx.x;
    const int e_base = blockIdx.x * TILE_E;
    const int warp = tid >> 5;
    const int lane = tid & 31;
    const int lq = lane & 3;
    const int lr = lane >> 2;
    const int m0 = warp * 16;

    #pragma unroll
    for (int t = 0; t < 8; t++) {
        int i = tid + t * 256;
        int k = i >> 5, n = i & 31;
        Wc[n * H1PH + k]        = __float2half(W2[i]);
        Wc[(32 + n) * H1PH + k] = __float2half(A2[i]);
    }
    #pragma unroll
    for (int t = 0; t < 2; t++) {
        int i = tid + t * 256;
        int k = i >> 4, n = i & 15;
        W3c[n * H2PH + k]        = __float2half(W3[i]);
        W3c[(16 + n) * H2PH + k] = __float2half(A3[i]);
    }

    // ---- Stage A: fp32 gather + layer1 -> fp16 h1s ----
    {
        const int l15 = lane & 15;
        int idx = 0;
        {
            int eg = e_base + warp * 16 + l15;
            if (eg < E) idx = (lane < 16) ? ei[eg] : ei[(size_t)E + eg];
            idx = min(max(idx, 0), MAX_NODES - 1);
        }
        const float4 b1v = *(const float4*)(b1 + 4 * l15);
        const bool lo = (lane < 16);

        #pragma unroll
        for (int p = 0; p < 8; p++) {
            const int srcA = __shfl_sync(0xffffffffu, idx, 2 * p);
            const int dstA = __shfl_sync(0xffffffffu, idx, 16 + 2 * p);
            const int srcB = __shfl_sync(0xffffffffu, idx, 2 * p + 1);
            const int dstB = __shfl_sync(0xffffffffu, idx, 17 + 2 * p);

            const float4 sA = *(const float4*)(g_P + (size_t)srcA * P_COLS + lane * 4);
            const float4 dA = *(const float4*)(g_P + (size_t)dstA * P_COLS + 128 + lane * 4);
            const float4 sB = *(const float4*)(g_P + (size_t)srcB * P_COLS + lane * 4);
            const float4 dB = *(const float4*)(g_P + (size_t)dstB * P_COLS + 128 + lane * 4);

            float4 wA, wB;
            wA.x = sA.x + dA.x; wA.y = sA.y + dA.y; wA.z = sA.z + dA.z; wA.w = sA.w + dA.w;
            wB.x = sB.x + dB.x; wB.y = sB.y + dB.y; wB.z = sB.z + dB.z; wB.w = sB.w + dB.w;

            float4 t, o;
            t.x = lo ? wB.x : wA.x;  t.y = lo ? wB.y : wA.y;
            t.z = lo ? wB.z : wA.z;  t.w = lo ? wB.w : wA.w;
            o.x = __shfl_xor_sync(0xffffffffu, t.x, 16);
            o.y = __shfl_xor_sync(0xffffffffu, t.y, 16);
            o.z = __shfl_xor_sync(0xffffffffu, t.z, 16);
            o.w = __shfl_xor_sync(0xffffffffu, t.w, 16);

            float4 w, a;
            w.x = lo ? wA.x : o.x;  a.x = lo ? o.x : wB.x;
            w.y = lo ? wA.y : o.y;  a.y = lo ? o.y : wB.y;
            w.z = lo ? wA.z : o.z;  a.z = lo ? o.z : wB.z;
            w.w = lo ? wA.w : o.w;  a.w = lo ? o.w : wB.w;

            const float h0  = fmaxf(fmaxf(w.x + b1v.x, 0.f) + a.x, 0.f);
            const float h1v = fmaxf(fmaxf(w.y + b1v.y, 0.f) + a.y, 0.f);
            const float h2v = fmaxf(fmaxf(w.z + b1v.z, 0.f) + a.z, 0.f);
            const float h3v = fmaxf(fmaxf(w.w + b1v.w, 0.f) + a.w, 0.f);

            const int e_loc = warp * 16 + 2 * p + (lo ? 0 : 1);
            __half2 q01 = __floats2half2_rn(h0, h1v);
            __half2 q23 = __floats2half2_rn(h2v, h3v);
            *(uint2*)(h1s + e_loc * H1PH + 4 * l15) = make_uint2(h2u(q01), h2u(q23));
        }
    }
    __syncthreads();

    // ---- Stage B: layer2 via mma ----
    const unsigned h1_a = sm_u32(h1s) +
        ((m0 + (lane & 15)) * H1PH + ((lane >> 4) << 3)) * 2;
    float acc[8][4];
    #pragma unroll
    for (int nb = 0; nb < 8; nb++)
        #pragma unroll
        for (int c = 0; c < 4; c++) acc[nb][c] = 0.f;

    #pragma unroll
    for (int kb = 0; kb < 4; kb++) {
        unsigned a0, a1, a2, a3;
        ldmat4(a0, a1, a2, a3, h1_a + kb * 32);
        #pragma unroll
        for (int nb = 0; nb < 8; nb++) {
            const __half* bp = Wc + (nb * 8 + lr) * H1PH + kb * 16 + 2 * lq;
            unsigned b0 = *(const unsigned*)bp;
            unsigned b1r = *(const unsigned*)(bp + 8);
            mma16816(acc[nb], a0, a1, a2, a3, b0, b1r);
        }
    }

    {
        unsigned regs[8];
        #pragma unroll
        for (int j = 0; j < 4; j++) {
            const float2 bb = __ldg((const float2*)(b2 + 8 * j + 2 * lq));
            float v0 = fmaxf(fmaxf(acc[j][0] + bb.x, 0.f) + acc[j + 4][0], 0.f);
            float v1 = fmaxf(fmaxf(acc[j][1] + bb.y, 0.f) + acc[j + 4][1], 0.f);
            float v2 = fmaxf(fmaxf(acc[j][2] + bb.x, 0.f) + acc[j + 4][2], 0.f);
            float v3 = fmaxf(fmaxf(acc[j][3] + bb.y, 0.f) + acc[j + 4][3], 0.f);
            regs[2 * j]     = h2u(__floats2half2_rn(v0, v1));
            regs[2 * j + 1] = h2u(__floats2half2_rn(v2, v3));
        }
        const unsigned h2_a = sm_u32(h2s) +
            ((m0 + (lane & 15)) * H2PH + ((lane >> 4) << 3)) * 2;
        stmat4(h2_a,      regs[0], regs[1], regs[2], regs[3]);
        stmat4(h2_a + 32, regs[4], regs[5], regs[6], regs[7]);
    }
    __syncwarp();

    // ---- Stage C: layer3 via mma + head ----
    const unsigned h2_ra = sm_u32(h2s) +
        ((m0 + (lane & 15)) * H2PH + ((lane >> 4) << 3)) * 2;
    float acc3[4][4];
    #pragma unroll
    for (int nb = 0; nb < 4; nb++)
        #pragma unroll
        for (int c = 0; c < 4; c++) acc3[nb][c] = 0.f;

    #pragma unroll
    for (int kb = 0; kb < 2; kb++) {
        unsigned a0, a1, a2, a3;
        ldmat4(a0, a1, a2, a3, h2_ra + kb * 32);
        #pragma unroll
        for (int nb = 0; nb < 4; nb++) {
            const __half* bp = W3c + (nb * 8 + lr) * H2PH + kb * 16 + 2 * lq;
            unsigned b0 = *(const unsigned*)bp;
            unsigned b1r = *(const unsigned*)(bp + 8);
            mma16816(acc3[nb], a0, a1, a2, a3, b0, b1r);
        }
    }

    float pr = 0.f, pr8 = 0.f;
    #pragma unroll
    for (int j = 0; j < 2; j++) {
        const float2 bb = __ldg((const float2*)(b3 + 8 * j + 2 * lq));
        const float2 wf = __ldg((const float2*)(Wf + 8 * j + 2 * lq));
        float v0 = fmaxf(fmaxf(acc3[j][0] + bb.x, 0.f) + acc3[j + 2][0], 0.f);
        float v1 = fmaxf(fmaxf(acc3[j][1] + bb.y, 0.f) + acc3[j + 2][1], 0.f);
        float v2 = fmaxf(fmaxf(acc3[j][2] + bb.x, 0.f) + acc3[j + 2][2], 0.f);
        float v3 = fmaxf(fmaxf(acc3[j][3] + bb.y, 0.f) + acc3[j + 2][3], 0.f);
        pr  += v0 * wf.x + v1 * wf.y;
        pr8 += v2 * wf.x + v3 * wf.y;
    }
    pr  += __shfl_xor_sync(0xffffffffu, pr, 1);
    pr  += __shfl_xor_sync(0xffffffffu, pr, 2);
    pr8 += __shfl_xor_sync(0xffffffffu, pr8, 1);
    pr8 += __shfl_xor_sync(0xffffffffu, pr8, 2);

    if (lq == 0) {
        const float bfv = __ldg(bf);
        int eg = e_base + m0 + lr;
        if (eg < E)     out[eg]     = 1.f / (1.f + expf(-(pr + bfv)));
        if (eg + 8 < E) out[eg + 8] = 1.f / (1.f + expf(-(pr8 + bfv)));
    }
}

// ---------------------------------------------------------------------------
extern "C" void kernel_launch(void* const* d_in, const int* in_sizes, int n_in,
                              void* d_out, int out_size) {
    const float* x  = (const float*)d_in[0];
    const int*   ei = (const int*)d_in[1];
    const float* W1 = (const float*)d_in[2];
    const float* b1 = (const float*)d_in[3];
    const float* A1 = (const float*)d_in[4];
    const float* W2 = (const float*)d_in[5];
    const float* b2 = (const float*)d_in[6];
    const float* A2 = (const float*)d_in[7];
    const float* W3 = (const float*)d_in[8];
    const float* b3 = (const float*)d_in[9];
    const float* A3 = (const float*)d_in[10];
    const float* Wf = (const float*)d_in[11];
    const float* bf = (const float*)d_in[12];
    float* out = (float*)d_out;

    const int n_nodes = in_sizes[0] / F_DIM;
    const int E = in_sizes[1] / 2;

    const int pre_smem = (2 * 128 * APH + 2 * 128 * BPH) * 2;   // 106496
    cudaFuncSetAttribute(precompute_hmma, cudaFuncAttributeMaxDynamicSharedMemorySize, pre_smem);
    precompute_hmma<<<(n_nodes + 127) / 128, 256, pre_smem>>>(x, W1, A1, n_nodes);

    const int smem_bytes = (9216 + 5120 + 4608 + 1280) * 2;     // 40448
    cudaFuncSetAttribute(edge_kernel7, cudaFuncAttributeMaxDynamicSharedMemorySize, smem_bytes);
    const int nb = (E + TILE_E - 1) / TILE_E;
    edge_kernel7<<<nb, 256, smem_bytes>>>(ei, b1, W2, b2, A2, W3, b3, A3, Wf, bf, out, E);
}

// round 11
// speedup vs baseline: 3.1125x; 1.1506x over previous
#include <cuda_runtime.h>
#include <cuda_fp16.h>
#include <math.h>

#define MAX_NODES 100000
#define F_DIM 128
// g_P fp16: [node][256 halves] = [PW_s+b1/2 (64) | PA_s(64) | PW_d+b1/2 (64) | PA_d(64)]
__device__ __half2 g_P[(size_t)MAX_NODES * 128];

// ---------------- mma / ldmatrix helpers ----------------
__device__ __forceinline__ unsigned sm_u32(const void* p) {
    unsigned a;
    asm("{ .reg .u64 t; cvta.to.shared.u64 t, %1; cvt.u32.u64 %0, t; }" : "=r"(a) : "l"(p));
    return a;
}
__device__ __forceinline__ void ldmat4(unsigned& r0, unsigned& r1, unsigned& r2, unsigned& r3,
                                       unsigned addr) {
    asm volatile("ldmatrix.sync.aligned.m8n8.x4.shared.b16 {%0,%1,%2,%3}, [%4];"
                 : "=r"(r0), "=r"(r1), "=r"(r2), "=r"(r3) : "r"(addr));
}
__device__ __forceinline__ void ldmat4t(unsigned& r0, unsigned& r1, unsigned& r2, unsigned& r3,
                                        unsigned addr) {
    asm volatile("ldmatrix.sync.aligned.m8n8.x4.trans.shared.b16 {%0,%1,%2,%3}, [%4];"
                 : "=r"(r0), "=r"(r1), "=r"(r2), "=r"(r3) : "r"(addr));
}
__device__ __forceinline__ void stmat4(unsigned addr, unsigned r0, unsigned r1,
                                       unsigned r2, unsigned r3) {
    asm volatile("stmatrix.sync.aligned.m8n8.x4.shared.b16 [%0], {%1,%2,%3,%4};"
                 :: "r"(addr), "r"(r0), "r"(r1), "r"(r2), "r"(r3) : "memory");
}
__device__ __forceinline__ void mma16816(float* c, unsigned a0, unsigned a1, unsigned a2,
                                         unsigned a3, unsigned b0, unsigned b1) {
    asm volatile(
        "mma.sync.aligned.m16n8k16.row.col.f32.f16.f16.f32 "
        "{%0,%1,%2,%3}, {%4,%5,%6,%7}, {%8,%9}, {%0,%1,%2,%3};"
        : "+f"(c[0]), "+f"(c[1]), "+f"(c[2]), "+f"(c[3])
        : "r"(a0), "r"(a1), "r"(a2), "r"(a3), "r"(b0), "r"(b1));
}
__device__ __forceinline__ unsigned h2u(__half2 h) { return *(unsigned*)&h; }
__device__ __forceinline__ __half2 u2h(unsigned u) { return *(__half2*)&u; }

// split a float4 into fp16 hi and lo half4s (as uint2 each)
__device__ __forceinline__ void split4(float4 v, uint2& hi, uint2& lo) {
    __half hx = __float2half_rn(v.x), hy = __float2half_rn(v.y);
    __half hz = __float2half_rn(v.z), hw = __float2half_rn(v.w);
    float lx = v.x - __half2float(hx), ly = v.y - __half2float(hy);
    float lz = v.z - __half2float(hz), lw = v.w - __half2float(hw);
    hi.x = h2u(__halves2half2(hx, hy));
    hi.y = h2u(__halves2half2(hz, hw));
    lo.x = h2u(__floats2half2_rn(lx, ly));
    lo.y = h2u(__floats2half2_rn(lz, lw));
}

// ---------------------------------------------------------------------------
// Kernel 1 (HMMA split-fp16): P[n,:] = x[n,:] @ [W1top|A1top|W1bot|A1bot]
// fp32-accurate via xh@Wh + xh@Wl + xl@Wh; output fp16 with b1/2 folded
// into the W quadrants (q even).
// ---------------------------------------------------------------------------
#define APH 136
#define BPH 72
__global__ __launch_bounds__(256, 2)
void precompute_hmma(const float* __restrict__ x,
                     const float* __restrict__ W1,
                     const float* __restrict__ A1,
                     const float* __restrict__ b1,
                     int n_nodes) {
    extern __shared__ __half ps[];
    __half* Ah = ps;                         // 128*136 = 17408
    __half* Al = ps + 17408;
    __half* Bh = ps + 2 * 17408;             // 128*72 = 9216
    __half* Bl = Bh + 9216;

    const int tid = threadIdx.x;
    const int m0b = blockIdx.x * 128;
    const int warp = tid >> 5;
    const int lane = tid & 31;
    const int lq = lane & 3;
    const int lr = lane >> 2;
    const int m0 = warp * 16;

    #pragma unroll
    for (int t = 0; t < 16; t++) {
        int i4 = tid + t * 256;               // 0..4095
        int m = i4 >> 5, k4 = i4 & 31;
        int gm = m0b + m;
        float4 v = (gm < n_nodes) ? *(const float4*)(x + (size_t)gm * F_DIM + k4 * 4)
                                  : make_float4(0.f, 0.f, 0.f, 0.f);
        uint2 hi, lo;
        split4(v, hi, lo);
        *(uint2*)(Ah + m * APH + k4 * 4) = hi;
        *(uint2*)(Al + m * APH + k4 * 4) = lo;
    }

    const unsigned a_hi = sm_u32(Ah) + ((m0 + (lane & 15)) * APH + ((lane >> 4) << 3)) * 2;
    const unsigned a_lo = sm_u32(Al) + ((m0 + (lane & 15)) * APH + ((lane >> 4) << 3)) * 2;
    const int bk  = (lane >> 3) & 1;
    const int bn8 = (lane >> 4) & 1;
    const int br  = lane & 7;
    const unsigned bh_base = sm_u32(Bh);
    const unsigned bl_base = sm_u32(Bl);
    __half* gph = (__half*)g_P;

    for (int q = 0; q < 4; q++) {
        __syncthreads();
        const float* srcq = ((q & 1) ? A1 : W1) + (size_t)(q >> 1) * 128 * 64;
        #pragma unroll
        for (int t = 0; t < 8; t++) {
            int i4 = tid + t * 256;           // 0..2047
            int k = i4 >> 4, n4 = i4 & 15;
            float4 v = *(const float4*)(srcq + k * 64 + n4 * 4);
            uint2 hi, lo;
            split4(v, hi, lo);
            *(uint2*)(Bh + k * BPH + n4 * 4) = hi;
            *(uint2*)(Bl + k * BPH + n4 * 4) = lo;
        }
        __syncthreads();

        float acc[8][4];
        #pragma unroll
        for (int nb = 0; nb < 8; nb++)
            #pragma unroll
            for (int c = 0; c < 4; c++) acc[nb][c] = 0.f;

        #pragma unroll
        for (int kb = 0; kb < 8; kb++) {
            unsigned ah0, ah1, ah2, ah3, al0, al1, al2, al3;
            ldmat4(ah0, ah1, ah2, ah3, a_hi + kb * 32);
            ldmat4(al0, al1, al2, al3, a_lo + kb * 32);
            #pragma unroll
            for (int nb2 = 0; nb2 < 4; nb2++) {
                const unsigned off =
                    ((kb * 16 + bk * 8 + br) * BPH + nb2 * 16 + bn8 * 8) * 2;
                unsigned bh0, bh1, bh2, bh3, bl0, bl1, bl2, bl3;
                ldmat4t(bh0, bh1, bh2, bh3, bh_base + off);
                ldmat4t(bl0, bl1, bl2, bl3, bl_base + off);
                mma16816(acc[2 * nb2],     ah0, ah1, ah2, ah3, bh0, bh1);
                mma16816(acc[2 * nb2],     ah0, ah1, ah2, ah3, bl0, bl1);
                mma16816(acc[2 * nb2],     al0, al1, al2, al3, bh0, bh1);
                mma16816(acc[2 * nb2 + 1], ah0, ah1, ah2, ah3, bh2, bh3);
                mma16816(acc[2 * nb2 + 1], ah0, ah1, ah2, ah3, bl2, bl3);
                mma16816(acc[2 * nb2 + 1], al0, al1, al2, al3, bh2, bh3);
            }
        }

        // epilogue: fold b1/2 into W quadrants; fp16 stores
        const int gm = m0b + m0 + lr;
        #pragma unroll
        for (int nb = 0; nb < 8; nb++) {
            const int n = q * 64 + nb * 8 + 2 * lq;
            float a0 = acc[nb][0], a1 = acc[nb][1], a2 = acc[nb][2], a3 = acc[nb][3];
            if (!(q & 1)) {
                const float2 bb = __ldg((const float2*)(b1 + nb * 8 + 2 * lq));
                a0 += 0.5f * bb.x; a1 += 0.5f * bb.y;
                a2 += 0.5f * bb.x; a3 += 0.5f * bb.y;
            }
            if (gm < n_nodes)
                *(unsigned*)(gph + (size_t)gm * 256 + n) = h2u(__floats2half2_rn(a0, a1));
            if (gm + 8 < n_nodes)
                *(unsigned*)(gph + (size_t)(gm + 8) * 256 + n) = h2u(__floats2half2_rn(a2, a3));
        }
    }
}

// ---------------------------------------------------------------------------
// Kernel 2 (v8): fp16 gather + half2 layer1, HMMA layers 2/3. Warp owns 16
// edges end-to-end. b1 is pre-folded into g_P.
// ---------------------------------------------------------------------------
#define TILE_E 128
#define H1PH 72
#define H2PH 40

__global__ __launch_bounds__(256, 4)
void edge_kernel8(const int* __restrict__ ei,
                  const float* __restrict__ W2, const float* __restrict__ b2,
                  const float* __restrict__ A2,
                  const float* __restrict__ W3, const float* __restrict__ b3,
                  const float* __restrict__ A3,
                  const float* __restrict__ Wf, const float* __restrict__ bf,
                  float* __restrict__ out, int E) {
    extern __shared__ __half hs[];
    __half* h1s = hs;                           // 128*72 = 9216
    __half* h2s = hs + 9216;                    // 128*40 = 5120
    __half* Wc  = hs + 9216 + 5120;             // 64*72  = 4608  [n][k]
    __half* W3c = hs + 9216 + 5120 + 4608;      // 32*40  = 1280  [n][k]

    const int tid = threadIdx.x;
    const int e_base = blockIdx.x * TILE_E;
    const int warp = tid >> 5;
    const int lane = tid & 31;
    const int lq = lane & 3;
    const int lr = lane >> 2;
    const int m0 = warp * 16;

    #pragma unroll
    for (int t = 0; t < 8; t++) {
        int i = tid + t * 256;
        int k = i >> 5, n = i & 31;
        Wc[n * H1PH + k]        = __float2half(W2[i]);
        Wc[(32 + n) * H1PH + k] = __float2half(A2[i]);
    }
    #pragma unroll
    for (int t = 0; t < 2; t++) {
        int i = tid + t * 256;
        int k = i >> 4, n = i & 15;
        W3c[n * H2PH + k]        = __float2half(W3[i]);
        W3c[(16 + n) * H2PH + k] = __float2half(A3[i]);
    }

    // ---- Stage A: fp16 gather + half2 layer1 -> h1s ----
    {
        const int l15 = lane & 15;
        int idx = 0;
        {
            int eg = e_base + warp * 16 + l15;
            if (eg < E) idx = (lane < 16) ? ei[eg] : ei[(size_t)E + eg];
            idx = min(max(idx, 0), MAX_NODES - 1);
        }
        const bool lo = (lane < 16);
        const __half* gp = (const __half*)g_P;
        const __half2 z = __float2half2_rn(0.f);

        #pragma unroll
        for (int p = 0; p < 8; p++) {
            const int srcA = __shfl_sync(0xffffffffu, idx, 2 * p);
            const int dstA = __shfl_sync(0xffffffffu, idx, 16 + 2 * p);
            const int srcB = __shfl_sync(0xffffffffu, idx, 2 * p + 1);
            const int dstB = __shfl_sync(0xffffffffu, idx, 17 + 2 * p);

            const uint2 sa = *(const uint2*)(gp + (size_t)srcA * 256 + lane * 4);
            const uint2 da = *(const uint2*)(gp + (size_t)dstA * 256 + 128 + lane * 4);
            const uint2 sb = *(const uint2*)(gp + (size_t)srcB * 256 + lane * 4);
            const uint2 db = *(const uint2*)(gp + (size_t)dstB * 256 + 128 + lane * 4);

            const unsigned wa0 = h2u(__hadd2(u2h(sa.x), u2h(da.x)));
            const unsigned wa1 = h2u(__hadd2(u2h(sa.y), u2h(da.y)));
            const unsigned wb0 = h2u(__hadd2(u2h(sb.x), u2h(db.x)));
            const unsigned wb1 = h2u(__hadd2(u2h(sb.y), u2h(db.y)));

            const unsigned t0 = lo ? wb0 : wa0;
            const unsigned t1 = lo ? wb1 : wa1;
            const unsigned o0 = __shfl_xor_sync(0xffffffffu, t0, 16);
            const unsigned o1 = __shfl_xor_sync(0xffffffffu, t1, 16);

            const __half2 w0 = u2h(lo ? wa0 : o0);
            const __half2 w1 = u2h(lo ? wa1 : o1);
            const __half2 a0 = u2h(lo ? o0 : wb0);
            const __half2 a1 = u2h(lo ? o1 : wb1);

            // bias already folded into w; h = relu(relu(w) + a)
            const __half2 h01 = __hmax2(__hadd2(__hmax2(w0, z), a0), z);
            const __half2 h23 = __hmax2(__hadd2(__hmax2(w1, z), a1), z);

            const int e_loc = warp * 16 + 2 * p + (lo ? 0 : 1);
            *(uint2*)(h1s + e_loc * H1PH + 4 * l15) = make_uint2(h2u(h01), h2u(h23));
        }
    }
    __syncthreads();

    // ---- Stage B: layer2 via mma ----
    const unsigned h1_a = sm_u32(h1s) +
        ((m0 + (lane & 15)) * H1PH + ((lane >> 4) << 3)) * 2;
    float acc[8][4];
    #pragma unroll
    for (int nb = 0; nb < 8; nb++)
        #pragma unroll
        for (int c = 0; c < 4; c++) acc[nb][c] = 0.f;

    #pragma unroll
    for (int kb = 0; kb < 4; kb++) {
        unsigned a0, a1, a2, a3;
        ldmat4(a0, a1, a2, a3, h1_a + kb * 32);
        #pragma unroll
        for (int nb = 0; nb < 8; nb++) {
            const __half* bp = Wc + (nb * 8 + lr) * H1PH + kb * 16 + 2 * lq;
            unsigned b0 = *(const unsigned*)bp;
            unsigned b1r = *(const unsigned*)(bp + 8);
            mma16816(acc[nb], a0, a1, a2, a3, b0, b1r);
        }
    }

    {
        unsigned regs[8];
        #pragma unroll
        for (int j = 0; j < 4; j++) {
            const float2 bb = __ldg((const float2*)(b2 + 8 * j + 2 * lq));
            float v0 = fmaxf(fmaxf(acc[j][0] + bb.x, 0.f) + acc[j + 4][0], 0.f);
            float v1 = fmaxf(fmaxf(acc[j][1] + bb.y, 0.f) + acc[j + 4][1], 0.f);
            float v2 = fmaxf(fmaxf(acc[j][2] + bb.x, 0.f) + acc[j + 4][2], 0.f);
            float v3 = fmaxf(fmaxf(acc[j][3] + bb.y, 0.f) + acc[j + 4][3], 0.f);
            regs[2 * j]     = h2u(__floats2half2_rn(v0, v1));
            regs[2 * j + 1] = h2u(__floats2half2_rn(v2, v3));
        }
        const unsigned h2_a = sm_u32(h2s) +
            ((m0 + (lane & 15)) * H2PH + ((lane >> 4) << 3)) * 2;
        stmat4(h2_a,      regs[0], regs[1], regs[2], regs[3]);
        stmat4(h2_a + 32, regs[4], regs[5], regs[6], regs[7]);
    }
    __syncwarp();

    // ---- Stage C: layer3 via mma + head ----
    const unsigned h2_ra = sm_u32(h2s) +
        ((m0 + (lane & 15)) * H2PH + ((lane >> 4) << 3)) * 2;
    float acc3[4][4];
    #pragma unroll
    for (int nb = 0; nb < 4; nb++)
        #pragma unroll
        for (int c = 0; c < 4; c++) acc3[nb][c] = 0.f;

    #pragma unroll
    for (int kb = 0; kb < 2; kb++) {
        unsigned a0, a1, a2, a3;
        ldmat4(a0, a1, a2, a3, h2_ra + kb * 32);
        #pragma unroll
        for (int nb = 0; nb < 4; nb++) {
            const __half* bp = W3c + (nb * 8 + lr) * H2PH + kb * 16 + 2 * lq;
            unsigned b0 = *(const unsigned*)bp;
            unsigned b1r = *(const unsigned*)(bp + 8);
            mma16816(acc3[nb], a0, a1, a2, a3, b0, b1r);
        }
    }

    float pr = 0.f, pr8 = 0.f;
    #pragma unroll
    for (int j = 0; j < 2; j++) {
        const float2 bb = __ldg((const float2*)(b3 + 8 * j + 2 * lq));
        const float2 wf = __ldg((const float2*)(Wf + 8 * j + 2 * lq));
        float v0 = fmaxf(fmaxf(acc3[j][0] + bb.x, 0.f) + acc3[j + 2][0], 0.f);
        float v1 = fmaxf(fmaxf(acc3[j][1] + bb.y, 0.f) + acc3[j + 2][1], 0.f);
        float v2 = fmaxf(fmaxf(acc3[j][2] + bb.x, 0.f) + acc3[j + 2][2], 0.f);
        float v3 = fmaxf(fmaxf(acc3[j][3] + bb.y, 0.f) + acc3[j + 2][3], 0.f);
        pr  += v0 * wf.x + v1 * wf.y;
        pr8 += v2 * wf.x + v3 * wf.y;
    }
    pr  += __shfl_xor_sync(0xffffffffu, pr, 1);
    pr  += __shfl_xor_sync(0xffffffffu, pr, 2);
    pr8 += __shfl_xor_sync(0xffffffffu, pr8, 1);
    pr8 += __shfl_xor_sync(0xffffffffu, pr8, 2);

    if (lq == 0) {
        const float bfv = __ldg(bf);
        int eg = e_base + m0 + lr;
        if (eg < E)     out[eg]     = 1.f / (1.f + expf(-(pr + bfv)));
        if (eg + 8 < E) out[eg + 8] = 1.f / (1.f + expf(-(pr8 + bfv)));
    }
}

// ---------------------------------------------------------------------------
extern "C" void kernel_launch(void* const* d_in, const int* in_sizes, int n_in,
                              void* d_out, int out_size) {
    const float* x  = (const float*)d_in[0];
    const int*   ei = (const int*)d_in[1];
    const float* W1 = (const float*)d_in[2];
    const float* b1 = (const float*)d_in[3];
    const float* A1 = (const float*)d_in[4];
    const float* W2 = (const float*)d_in[5];
    const float* b2 = (const float*)d_in[6];
    const float* A2 = (const float*)d_in[7];
    const float* W3 = (const float*)d_in[8];
    const float* b3 = (const float*)d_in[9];
    const float* A3 = (const float*)d_in[10];
    const float* Wf = (const float*)d_in[11];
    const float* bf = (const float*)d_in[12];
    float* out = (float*)d_out;

    const int n_nodes = in_sizes[0] / F_DIM;
    const int E = in_sizes[1] / 2;

    const int pre_smem = (2 * 128 * APH + 2 * 128 * BPH) * 2;   // 106496
    cudaFuncSetAttribute(precompute_hmma, cudaFuncAttributeMaxDynamicSharedMemorySize, pre_smem);
    precompute_hmma<<<(n_nodes + 127) / 128, 256, pre_smem>>>(x, W1, A1, b1, n_nodes);

    const int smem_bytes = (9216 + 5120 + 4608 + 1280) * 2;     // 40448
    cudaFuncSetAttribute(edge_kernel8, cudaFuncAttributeMaxDynamicSharedMemorySize, smem_bytes);
    const int nb = (E + TILE_E - 1) / TILE_E;
    edge_kernel8<<<nb, 256, smem_bytes>>>(ei, W2, b2, A2, W3, b3, A3, Wf, bf, out, E);
}

// round 12
// speedup vs baseline: 3.5428x; 1.1382x over previous
#include <cuda_runtime.h>
#include <cuda_fp16.h>
#include <math.h>

#define MAX_NODES 100000
#define F_DIM 128
// g_P fp16: [node][256 halves] = [PW_s+b1/2 (64) | PA_s(64) | PW_d+b1/2 (64) | PA_d(64)]
__device__ __half2 g_P[(size_t)MAX_NODES * 128];

// ---------------- mma / ldmatrix helpers ----------------
__device__ __forceinline__ unsigned sm_u32(const void* p) {
    unsigned a;
    asm("{ .reg .u64 t; cvta.to.shared.u64 t, %1; cvt.u32.u64 %0, t; }" : "=r"(a) : "l"(p));
    return a;
}
__device__ __forceinline__ void ldmat4(unsigned& r0, unsigned& r1, unsigned& r2, unsigned& r3,
                                       unsigned addr) {
    asm volatile("ldmatrix.sync.aligned.m8n8.x4.shared.b16 {%0,%1,%2,%3}, [%4];"
                 : "=r"(r0), "=r"(r1), "=r"(r2), "=r"(r3) : "r"(addr));
}
__device__ __forceinline__ void ldmat4t(unsigned& r0, unsigned& r1, unsigned& r2, unsigned& r3,
                                        unsigned addr) {
    asm volatile("ldmatrix.sync.aligned.m8n8.x4.trans.shared.b16 {%0,%1,%2,%3}, [%4];"
                 : "=r"(r0), "=r"(r1), "=r"(r2), "=r"(r3) : "r"(addr));
}
__device__ __forceinline__ void stmat4(unsigned addr, unsigned r0, unsigned r1,
                                       unsigned r2, unsigned r3) {
    asm volatile("stmatrix.sync.aligned.m8n8.x4.shared.b16 [%0], {%1,%2,%3,%4};"
                 :: "r"(addr), "r"(r0), "r"(r1), "r"(r2), "r"(r3) : "memory");
}
__device__ __forceinline__ void mma16816(float* c, unsigned a0, unsigned a1, unsigned a2,
                                         unsigned a3, unsigned b0, unsigned b1) {
    asm volatile(
        "mma.sync.aligned.m16n8k16.row.col.f32.f16.f16.f32 "
        "{%0,%1,%2,%3}, {%4,%5,%6,%7}, {%8,%9}, {%0,%1,%2,%3};"
        : "+f"(c[0]), "+f"(c[1]), "+f"(c[2]), "+f"(c[3])
        : "r"(a0), "r"(a1), "r"(a2), "r"(a3), "r"(b0), "r"(b1));
}
__device__ __forceinline__ unsigned h2u(__half2 h) { return *(unsigned*)&h; }
__device__ __forceinline__ __half2 u2h(unsigned u) { return *(__half2*)&u; }

// ---------------------------------------------------------------------------
// Kernel 1 (plain fp16 HMMA): P[n,:] = x[n,:] @ [W1top|A1top|W1bot|A1bot]
// fp16 inputs, fp32 accum; b1/2 folded into W quadrants; fp16 output.
// smem (halves): Ah[128][136] + Bh[128][72] = 53248 B -> 4 blocks/SM.
// ---------------------------------------------------------------------------
#define APH 136
#define BPH 72
__global__ __launch_bounds__(256, 4)
void precompute_hmma16(const float* __restrict__ x,
                       const float* __restrict__ W1,
                       const float* __restrict__ A1,
                       const float* __restrict__ b1,
                       int n_nodes) {
    extern __shared__ __half ps[];
    __half* Ah = ps;                         // 128*136 = 17408
    __half* Bh = ps + 17408;                 // 128*72  = 9216

    const int tid = threadIdx.x;
    const int m0b = blockIdx.x * 128;
    const int warp = tid >> 5;
    const int lane = tid & 31;
    const int lq = lane & 3;
    const int lr = lane >> 2;
    const int m0 = warp * 16;

    // ---- stage A: x tile -> fp16, [m][k] pitch 136 ----
    #pragma unroll
    for (int t = 0; t < 16; t++) {
        int i4 = tid + t * 256;               // 0..4095
        int m = i4 >> 5, k4 = i4 & 31;
        int gm = m0b + m;
        float4 v = (gm < n_nodes) ? *(const float4*)(x + (size_t)gm * F_DIM + k4 * 4)
                                  : make_float4(0.f, 0.f, 0.f, 0.f);
        uint2 hv;
        hv.x = h2u(__floats2half2_rn(v.x, v.y));
        hv.y = h2u(__floats2half2_rn(v.z, v.w));
        *(uint2*)(Ah + m * APH + k4 * 4) = hv;
    }

    const unsigned a_hi = sm_u32(Ah) + ((m0 + (lane & 15)) * APH + ((lane >> 4) << 3)) * 2;
    const int bk  = (lane >> 3) & 1;
    const int bn8 = (lane >> 4) & 1;
    const int br  = lane & 7;
    const unsigned bh_base = sm_u32(Bh);
    __half* gph = (__half*)g_P;

    for (int q = 0; q < 4; q++) {
        __syncthreads();
        const float* srcq = ((q & 1) ? A1 : W1) + (size_t)(q >> 1) * 128 * 64;
        #pragma unroll
        for (int t = 0; t < 8; t++) {
            int i4 = tid + t * 256;           // 0..2047
            int k = i4 >> 4, n4 = i4 & 15;
            float4 v = *(const float4*)(srcq + k * 64 + n4 * 4);
            uint2 hv;
            hv.x = h2u(__floats2half2_rn(v.x, v.y));
            hv.y = h2u(__floats2half2_rn(v.z, v.w));
            *(uint2*)(Bh + k * BPH + n4 * 4) = hv;
        }
        __syncthreads();

        float acc[8][4];
        #pragma unroll
        for (int nb = 0; nb < 8; nb++)
            #pragma unroll
            for (int c = 0; c < 4; c++) acc[nb][c] = 0.f;

        #pragma unroll
        for (int kb = 0; kb < 8; kb++) {
            unsigned a0, a1, a2, a3;
            ldmat4(a0, a1, a2, a3, a_hi + kb * 32);
            #pragma unroll
            for (int nb2 = 0; nb2 < 4; nb2++) {
                const unsigned off =
                    ((kb * 16 + bk * 8 + br) * BPH + nb2 * 16 + bn8 * 8) * 2;
                unsigned b0, b1r, b2r, b3r;
                ldmat4t(b0, b1r, b2r, b3r, bh_base + off);
                mma16816(acc[2 * nb2],     a0, a1, a2, a3, b0, b1r);
                mma16816(acc[2 * nb2 + 1], a0, a1, a2, a3, b2r, b3r);
            }
        }

        // epilogue: fold b1/2 into W quadrants; fp16 stores
        const int gm = m0b + m0 + lr;
        #pragma unroll
        for (int nb = 0; nb < 8; nb++) {
            const int n = q * 64 + nb * 8 + 2 * lq;
            float a0 = acc[nb][0], a1 = acc[nb][1], a2 = acc[nb][2], a3 = acc[nb][3];
            if (!(q & 1)) {
                const float2 bb = __ldg((const float2*)(b1 + nb * 8 + 2 * lq));
                a0 += 0.5f * bb.x; a1 += 0.5f * bb.y;
                a2 += 0.5f * bb.x; a3 += 0.5f * bb.y;
            }
            if (gm < n_nodes)
                *(unsigned*)(gph + (size_t)gm * 256 + n) = h2u(__floats2half2_rn(a0, a1));
            if (gm + 8 < n_nodes)
                *(unsigned*)(gph + (size_t)(gm + 8) * 256 + n) = h2u(__floats2half2_rn(a2, a3));
        }
    }
}

// ---------------------------------------------------------------------------
// Kernel 2 (v9): fp16 gather + half2 layer1; HMMA layers 2/3 with B-fragments
// via ldmatrix.trans (Wc/W3c stored [k][n]). Warp owns 16 edges end-to-end.
// ---------------------------------------------------------------------------
#define TILE_E 128
#define H1PH 72   // h1s pitch ([m][k]) and Wc pitch ([k][n])
#define H2PH 40   // h2s pitch ([m][k]) and W3c pitch ([k][n])

__global__ __launch_bounds__(256, 4)
void edge_kernel9(const int* __restrict__ ei,
                  const float* __restrict__ W2, const float* __restrict__ b2,
                  const float* __restrict__ A2,
                  const float* __restrict__ W3, const float* __restrict__ b3,
                  const float* __restrict__ A3,
                  const float* __restrict__ Wf, const float* __restrict__ bf,
                  float* __restrict__ out, int E) {
    extern __shared__ __half hs[];
    __half* h1s = hs;                           // 128*72 = 9216
    __half* h2s = hs + 9216;                    // 128*40 = 5120
    __half* Wc  = hs + 9216 + 5120;             // 64*72  = 4608  [k][n] = [W2|A2]
    __half* W3c = hs + 9216 + 5120 + 4608;      // 32*40  = 1280  [k][n] = [W3|A3]

    const int tid = threadIdx.x;
    const int e_base = blockIdx.x * TILE_E;
    const int warp = tid >> 5;
    const int lane = tid & 31;
    const int lq = lane & 3;
    const int lr = lane >> 2;
    const int m0 = warp * 16;

    // ---- weight staging: [k][n] layout ----
    #pragma unroll
    for (int t = 0; t < 8; t++) {
        int i = tid + t * 256;           // 0..2047 = k*32+n
        int k = i >> 5, n = i & 31;
        Wc[k * H1PH + n]      = __float2half(W2[i]);
        Wc[k * H1PH + 32 + n] = __float2half(A2[i]);
    }
    #pragma unroll
    for (int t = 0; t < 2; t++) {
        int i = tid + t * 256;           // 0..511 = k*16+n
        int k = i >> 4, n = i & 15;
        W3c[k * H2PH + n]      = __float2half(W3[i]);
        W3c[k * H2PH + 16 + n] = __float2half(A3[i]);
    }

    // ---- Stage A: fp16 gather + half2 layer1 -> h1s ----
    {
        const int l15 = lane & 15;
        int idx = 0;
        {
            int eg = e_base + warp * 16 + l15;
            if (eg < E) idx = (lane < 16) ? ei[eg] : ei[(size_t)E + eg];
            idx = min(max(idx, 0), MAX_NODES - 1);
        }
        const bool lo = (lane < 16);
        const __half* gp = (const __half*)g_P;
        const __half2 z = __float2half2_rn(0.f);

        #pragma unroll
        for (int p = 0; p < 8; p++) {
            const int srcA = __shfl_sync(0xffffffffu, idx, 2 * p);
            const int dstA = __shfl_sync(0xffffffffu, idx, 16 + 2 * p);
            const int srcB = __shfl_sync(0xffffffffu, idx, 2 * p + 1);
            const int dstB = __shfl_sync(0xffffffffu, idx, 17 + 2 * p);

            const uint2 sa = *(const uint2*)(gp + (size_t)srcA * 256 + lane * 4);
            const uint2 da = *(const uint2*)(gp + (size_t)dstA * 256 + 128 + lane * 4);
            const uint2 sb = *(const uint2*)(gp + (size_t)srcB * 256 + lane * 4);
            const uint2 db = *(const uint2*)(gp + (size_t)dstB * 256 + 128 + lane * 4);

            const unsigned wa0 = h2u(__hadd2(u2h(sa.x), u2h(da.x)));
            const unsigned wa1 = h2u(__hadd2(u2h(sa.y), u2h(da.y)));
            const unsigned wb0 = h2u(__hadd2(u2h(sb.x), u2h(db.x)));
            const unsigned wb1 = h2u(__hadd2(u2h(sb.y), u2h(db.y)));

            const unsigned t0 = lo ? wb0 : wa0;
            const unsigned t1 = lo ? wb1 : wa1;
            const unsigned o0 = __shfl_xor_sync(0xffffffffu, t0, 16);
            const unsigned o1 = __shfl_xor_sync(0xffffffffu, t1, 16);

            const __half2 w0 = u2h(lo ? wa0 : o0);
            const __half2 w1 = u2h(lo ? wa1 : o1);
            const __half2 a0 = u2h(lo ? o0 : wb0);
            const __half2 a1 = u2h(lo ? o1 : wb1);

            const __half2 h01 = __hmax2(__hadd2(__hmax2(w0, z), a0), z);
            const __half2 h23 = __hmax2(__hadd2(__hmax2(w1, z), a1), z);

            const int e_loc = warp * 16 + 2 * p + (lo ? 0 : 1);
            *(uint2*)(h1s + e_loc * H1PH + 4 * (lane & 15)) = make_uint2(h2u(h01), h2u(h23));
        }
    }
    __syncthreads();

    const int bk  = (lane >> 3) & 1;
    const int bn8 = (lane >> 4) & 1;
    const int br  = lane & 7;

    // ---- Stage B: layer2 via mma, B frags via ldmatrix.trans ----
    const unsigned h1_a = sm_u32(h1s) +
        ((m0 + (lane & 15)) * H1PH + ((lane >> 4) << 3)) * 2;
    const unsigned wc_base = sm_u32(Wc);
    float acc[8][4];
    #pragma unroll
    for (int nb = 0; nb < 8; nb++)
        #pragma unroll
        for (int c = 0; c < 4; c++) acc[nb][c] = 0.f;

    #pragma unroll
    for (int kb = 0; kb < 4; kb++) {
        unsigned a0, a1, a2, a3;
        ldmat4(a0, a1, a2, a3, h1_a + kb * 32);
        #pragma unroll
        for (int nb2 = 0; nb2 < 4; nb2++) {
            const unsigned off =
                ((kb * 16 + bk * 8 + br) * H1PH + nb2 * 16 + bn8 * 8) * 2;
            unsigned b0, b1r, b2r, b3r;
            ldmat4t(b0, b1r, b2r, b3r, wc_base + off);
            mma16816(acc[2 * nb2],     a0, a1, a2, a3, b0, b1r);
            mma16816(acc[2 * nb2 + 1], a0, a1, a2, a3, b2r, b3r);
        }
    }

    {
        unsigned regs[8];
        #pragma unroll
        for (int j = 0; j < 4; j++) {
            const float2 bb = __ldg((const float2*)(b2 + 8 * j + 2 * lq));
            float v0 = fmaxf(fmaxf(acc[j][0] + bb.x, 0.f) + acc[j + 4][0], 0.f);
            float v1 = fmaxf(fmaxf(acc[j][1] + bb.y, 0.f) + acc[j + 4][1], 0.f);
            float v2 = fmaxf(fmaxf(acc[j][2] + bb.x, 0.f) + acc[j + 4][2], 0.f);
            float v3 = fmaxf(fmaxf(acc[j][3] + bb.y, 0.f) + acc[j + 4][3], 0.f);
            regs[2 * j]     = h2u(__floats2half2_rn(v0, v1));
            regs[2 * j + 1] = h2u(__floats2half2_rn(v2, v3));
        }
        const unsigned h2_a = sm_u32(h2s) +
            ((m0 + (lane & 15)) * H2PH + ((lane >> 4) << 3)) * 2;
        stmat4(h2_a,      regs[0], regs[1], regs[2], regs[3]);
        stmat4(h2_a + 32, regs[4], regs[5], regs[6], regs[7]);
    }
    __syncwarp();

    // ---- Stage C: layer3 via mma + head ----
    const unsigned h2_ra = sm_u32(h2s) +
        ((m0 + (lane & 15)) * H2PH + ((lane >> 4) << 3)) * 2;
    const unsigned w3_base = sm_u32(W3c);
    float acc3[4][4];
    #pragma unroll
    for (int nb = 0; nb < 4; nb++)
        #pragma unroll
        for (int c = 0; c < 4; c++) acc3[nb][c] = 0.f;

    #pragma unroll
    for (int kb = 0; kb < 2; kb++) {
        unsigned a0, a1, a2, a3;
        ldmat4(a0, a1, a2, a3, h2_ra + kb * 32);
        #pragma unroll
        for (int nb2 = 0; nb2 < 2; nb2++) {
            const unsigned off =
                ((kb * 16 + bk * 8 + br) * H2PH + nb2 * 16 + bn8 * 8) * 2;
            unsigned b0, b1r, b2r, b3r;
            ldmat4t(b0, b1r, b2r, b3r, w3_base + off);
            mma16816(acc3[2 * nb2],     a0, a1, a2, a3, b0, b1r);
            mma16816(acc3[2 * nb2 + 1], a0, a1, a2, a3, b2r, b3r);
        }
    }

    float pr = 0.f, pr8 = 0.f;
    #pragma unroll
    for (int j = 0; j < 2; j++) {
        const float2 bb = __ldg((const float2*)(b3 + 8 * j + 2 * lq));
        const float2 wf = __ldg((const float2*)(Wf + 8 * j + 2 * lq));
        float v0 = fmaxf(fmaxf(acc3[j][0] + bb.x, 0.f) + acc3[j + 2][0], 0.f);
        float v1 = fmaxf(fmaxf(acc3[j][1] + bb.y, 0.f) + acc3[j + 2][1], 0.f);
        float v2 = fmaxf(fmaxf(acc3[j][2] + bb.x, 0.f) + acc3[j + 2][2], 0.f);
        float v3 = fmaxf(fmaxf(acc3[j][3] + bb.y, 0.f) + acc3[j + 2][3], 0.f);
        pr  += v0 * wf.x + v1 * wf.y;
        pr8 += v2 * wf.x + v3 * wf.y;
    }
    pr  += __shfl_xor_sync(0xffffffffu, pr, 1);
    pr  += __shfl_xor_sync(0xffffffffu, pr, 2);
    pr8 += __shfl_xor_sync(0xffffffffu, pr8, 1);
    pr8 += __shfl_xor_sync(0xffffffffu, pr8, 2);

    if (lq == 0) {
        const float bfv = __ldg(bf);
        int eg = e_base + m0 + lr;
        if (eg < E)     out[eg]     = 1.f / (1.f + expf(-(pr + bfv)));
        if (eg + 8 < E) out[eg + 8] = 1.f / (1.f + expf(-(pr8 + bfv)));
    }
}

// ---------------------------------------------------------------------------
extern "C" void kernel_launch(void* const* d_in, const int* in_sizes, int n_in,
                              void* d_out, int out_size) {
    const float* x  = (const float*)d_in[0];
    const int*   ei = (const int*)d_in[1];
    const float* W1 = (const float*)d_in[2];
    const float* b1 = (const float*)d_in[3];
    const float* A1 = (const float*)d_in[4];
    const float* W2 = (const float*)d_in[5];
    const float* b2 = (const float*)d_in[6];
    const float* A2 = (const float*)d_in[7];
    const float* W3 = (const float*)d_in[8];
    const float* b3 = (const float*)d_in[9];
    const float* A3 = (const float*)d_in[10];
    const float* Wf = (const float*)d_in[11];
    const float* bf = (const float*)d_in[12];
    float* out = (float*)d_out;

    const int n_nodes = in_sizes[0] / F_DIM;
    const int E = in_sizes[1] / 2;

    const int pre_smem = (128 * APH + 128 * BPH) * 2;           // 53248
    cudaFuncSetAttribute(precompute_hmma16, cudaFuncAttributeMaxDynamicSharedMemorySize, pre_smem);
    precompute_hmma16<<<(n_nodes + 127) / 128, 256, pre_smem>>>(x, W1, A1, b1, n_nodes);

    const int smem_bytes = (9216 + 5120 + 4608 + 1280) * 2;     // 40448
    cudaFuncSetAttribute(edge_kernel9, cudaFuncAttributeMaxDynamicSharedMemorySize, smem_bytes);
    const int nb = (E + TILE_E - 1) / TILE_E;
    edge_kernel9<<<nb, 256, smem_bytes>>>(ei, W2, b2, A2, W3, b3, A3, Wf, bf, out, E);
}

// round 13
// speedup vs baseline: 4.0796x; 1.1515x over previous
#include <cuda_runtime.h>
#include <cuda_fp16.h>
#include <math.h>

#define MAX_NODES 100000
#define F_DIM 128
// g_P fp16: [node][256 halves] = [PW_s+b1/2 (64) | PA_s(64) | PW_d+b1/2 (64) | PA_d(64)]
__device__ __half2 g_P[(size_t)MAX_NODES * 128];

// ---------------- mma / ldmatrix helpers ----------------
__device__ __forceinline__ unsigned sm_u32(const void* p) {
    unsigned a;
    asm("{ .reg .u64 t; cvta.to.shared.u64 t, %1; cvt.u32.u64 %0, t; }" : "=r"(a) : "l"(p));
    return a;
}
__device__ __forceinline__ void ldmat4(unsigned& r0, unsigned& r1, unsigned& r2, unsigned& r3,
                                       unsigned addr) {
    asm volatile("ldmatrix.sync.aligned.m8n8.x4.shared.b16 {%0,%1,%2,%3}, [%4];"
                 : "=r"(r0), "=r"(r1), "=r"(r2), "=r"(r3) : "r"(addr));
}
__device__ __forceinline__ void ldmat4t(unsigned& r0, unsigned& r1, unsigned& r2, unsigned& r3,
                                        unsigned addr) {
    asm volatile("ldmatrix.sync.aligned.m8n8.x4.trans.shared.b16 {%0,%1,%2,%3}, [%4];"
                 : "=r"(r0), "=r"(r1), "=r"(r2), "=r"(r3) : "r"(addr));
}
__device__ __forceinline__ void stmat4(unsigned addr, unsigned r0, unsigned r1,
                                       unsigned r2, unsigned r3) {
    asm volatile("stmatrix.sync.aligned.m8n8.x4.shared.b16 [%0], {%1,%2,%3,%4};"
                 :: "r"(addr), "r"(r0), "r"(r1), "r"(r2), "r"(r3) : "memory");
}
__device__ __forceinline__ void mma16816(float* c, unsigned a0, unsigned a1, unsigned a2,
                                         unsigned a3, unsigned b0, unsigned b1) {
    asm volatile(
        "mma.sync.aligned.m16n8k16.row.col.f32.f16.f16.f32 "
        "{%0,%1,%2,%3}, {%4,%5,%6,%7}, {%8,%9}, {%0,%1,%2,%3};"
        : "+f"(c[0]), "+f"(c[1]), "+f"(c[2]), "+f"(c[3])
        : "r"(a0), "r"(a1), "r"(a2), "r"(a3), "r"(b0), "r"(b1));
}
__device__ __forceinline__ unsigned h2u(__half2 h) { return *(unsigned*)&h; }
__device__ __forceinline__ __half2 u2h(unsigned u) { return *(__half2*)&u; }

// ---------------------------------------------------------------------------
// Kernel 1 (fp16 HMMA, coalesced epilogue): P = x @ [W1t|A1t|W1b|A1b]
// fp16 in, fp32 accum; b1/2 folded into W quadrants; fragments go through
// stmatrix -> OutS smem tile -> coalesced STG.64.
// smem (halves): Ah[128][136] + Bh[128][72] + OutS[128][72] = 71680 B.
// ---------------------------------------------------------------------------
#define APH 136
#define BPH 72
#define OPH 72
__global__ __launch_bounds__(256, 3)
void precompute_hmma16(const float* __restrict__ x,
                       const float* __restrict__ W1,
                       const float* __restrict__ A1,
                       const float* __restrict__ b1,
                       int n_nodes) {
    extern __shared__ __half ps[];
    __half* Ah   = ps;                        // 128*136 = 17408
    __half* Bh   = ps + 17408;                // 128*72  = 9216
    __half* OutS = ps + 17408 + 9216;         // 128*72  = 9216

    const int tid = threadIdx.x;
    const int m0b = blockIdx.x * 128;
    const int warp = tid >> 5;
    const int lane = tid & 31;
    const int lq = lane & 3;
    const int m0 = warp * 16;

    // ---- stage A: x tile -> fp16, [m][k] pitch 136 ----
    #pragma unroll
    for (int t = 0; t < 16; t++) {
        int i4 = tid + t * 256;               // 0..4095
        int m = i4 >> 5, k4 = i4 & 31;
        int gm = m0b + m;
        float4 v = (gm < n_nodes) ? *(const float4*)(x + (size_t)gm * F_DIM + k4 * 4)
                                  : make_float4(0.f, 0.f, 0.f, 0.f);
        uint2 hv;
        hv.x = h2u(__floats2half2_rn(v.x, v.y));
        hv.y = h2u(__floats2half2_rn(v.z, v.w));
        *(uint2*)(Ah + m * APH + k4 * 4) = hv;
    }

    const unsigned a_hi = sm_u32(Ah) + ((m0 + (lane & 15)) * APH + ((lane >> 4) << 3)) * 2;
    const unsigned o_a  = sm_u32(OutS) + ((m0 + (lane & 15)) * OPH + ((lane >> 4) << 3)) * 2;
    const int bk  = (lane >> 3) & 1;
    const int bn8 = (lane >> 4) & 1;
    const int br  = lane & 7;
    const unsigned bh_base = sm_u32(Bh);
    __half* gph = (__half*)g_P;

    for (int q = 0; q < 4; q++) {
        __syncthreads();   // prior OutS reads done / A ready
        const float* srcq = ((q & 1) ? A1 : W1) + (size_t)(q >> 1) * 128 * 64;
        #pragma unroll
        for (int t = 0; t < 8; t++) {
            int i4 = tid + t * 256;           // 0..2047
            int k = i4 >> 4, n4 = i4 & 15;
            float4 v = *(const float4*)(srcq + k * 64 + n4 * 4);
            uint2 hv;
            hv.x = h2u(__floats2half2_rn(v.x, v.y));
            hv.y = h2u(__floats2half2_rn(v.z, v.w));
            *(uint2*)(Bh + k * BPH + n4 * 4) = hv;
        }
        __syncthreads();

        float acc[8][4];
        #pragma unroll
        for (int nb = 0; nb < 8; nb++)
            #pragma unroll
            for (int c = 0; c < 4; c++) acc[nb][c] = 0.f;

        #pragma unroll
        for (int kb = 0; kb < 8; kb++) {
            unsigned a0, a1, a2, a3;
            ldmat4(a0, a1, a2, a3, a_hi + kb * 32);
            #pragma unroll
            for (int nb2 = 0; nb2 < 4; nb2++) {
                const unsigned off =
                    ((kb * 16 + bk * 8 + br) * BPH + nb2 * 16 + bn8 * 8) * 2;
                unsigned b0, b1r, b2r, b3r;
                ldmat4t(b0, b1r, b2r, b3r, bh_base + off);
                mma16816(acc[2 * nb2],     a0, a1, a2, a3, b0, b1r);
                mma16816(acc[2 * nb2 + 1], a0, a1, a2, a3, b2r, b3r);
            }
        }

        // epilogue: fold b1/2 (W quadrants), pack fp16, stmatrix to OutS
        {
            unsigned regs[16];
            #pragma unroll
            for (int nb = 0; nb < 8; nb++) {
                float a0 = acc[nb][0], a1 = acc[nb][1], a2 = acc[nb][2], a3 = acc[nb][3];
                if (!(q & 1)) {
                    const float2 bb = __ldg((const float2*)(b1 + nb * 8 + 2 * lq));
                    a0 += 0.5f * bb.x; a1 += 0.5f * bb.y;
                    a2 += 0.5f * bb.x; a3 += 0.5f * bb.y;
                }
                regs[2 * nb]     = h2u(__floats2half2_rn(a0, a1));
                regs[2 * nb + 1] = h2u(__floats2half2_rn(a2, a3));
            }
            stmat4(o_a,      regs[0],  regs[1],  regs[2],  regs[3]);   // cols 0-15
            stmat4(o_a + 32, regs[4],  regs[5],  regs[6],  regs[7]);   // cols 16-31
            stmat4(o_a + 64, regs[8],  regs[9],  regs[10], regs[11]);  // cols 32-47
            stmat4(o_a + 96, regs[12], regs[13], regs[14], regs[15]);  // cols 48-63
        }
        __syncthreads();

        // coalesced store: 16 lanes = one 128B row-half
        #pragma unroll
        for (int t = 0; t < 8; t++) {
            int i = tid + t * 256;            // 0..2047
            int r = i >> 4, c = i & 15;
            int gm = m0b + r;
            if (gm < n_nodes)
                *(uint2*)(gph + (size_t)gm * 256 + q * 64 + c * 4) =
                    *(const uint2*)(OutS + r * OPH + c * 4);
        }
    }
}

// ---------------------------------------------------------------------------
// Kernel 2 (v10): fp16 gather (32-bit byte offsets) + half2 layer1; HMMA
// layers 2/3 with B-frags via ldmatrix.trans. Warp owns 16 edges end-to-end.
// ---------------------------------------------------------------------------
#define TILE_E 128
#define H1PH 72   // h1s pitch ([m][k]) and Wc pitch ([k][n])
#define H2PH 40   // h2s pitch ([m][k]) and W3c pitch ([k][n])

__global__ __launch_bounds__(256, 4)
void edge_kernel10(const int* __restrict__ ei,
                   const float* __restrict__ W2, const float* __restrict__ b2,
                   const float* __restrict__ A2,
                   const float* __restrict__ W3, const float* __restrict__ b3,
                   const float* __restrict__ A3,
                   const float* __restrict__ Wf, const float* __restrict__ bf,
                   float* __restrict__ out, int E) {
    extern __shared__ __half hs[];
    __half* h1s = hs;                           // 128*72 = 9216
    __half* h2s = hs + 9216;                    // 128*40 = 5120
    __half* Wc  = hs + 9216 + 5120;             // 64*72  = 4608  [k][n] = [W2|A2]
    __half* W3c = hs + 9216 + 5120 + 4608;      // 32*40  = 1280  [k][n] = [W3|A3]

    const int tid = threadIdx.x;
    const int e_base = blockIdx.x * TILE_E;
    const int warp = tid >> 5;
    const int lane = tid & 31;
    const int lq = lane & 3;
    const int lr = lane >> 2;
    const int m0 = warp * 16;

    // ---- weight staging: [k][n] layout ----
    #pragma unroll
    for (int t = 0; t < 8; t++) {
        int i = tid + t * 256;           // 0..2047 = k*32+n
        int k = i >> 5, n = i & 31;
        Wc[k * H1PH + n]      = __float2half(W2[i]);
        Wc[k * H1PH + 32 + n] = __float2half(A2[i]);
    }
    #pragma unroll
    for (int t = 0; t < 2; t++) {
        int i = tid + t * 256;           // 0..511 = k*16+n
        int k = i >> 4, n = i & 15;
        W3c[k * H2PH + n]      = __float2half(W3[i]);
        W3c[k * H2PH + 16 + n] = __float2half(A3[i]);
    }

    // ---- Stage A: fp16 gather (32-bit offsets) + half2 layer1 -> h1s ----
    {
        const int l15 = lane & 15;
        unsigned off = 0;
        {
            int eg = e_base + warp * 16 + l15;
            int idx = 0;
            if (eg < E) idx = (lane < 16) ? ei[eg] : ei[(size_t)E + eg];
            idx = min(max(idx, 0), MAX_NODES - 1);
            off = (unsigned)idx * 512u;         // byte offset into g_P
        }
        const bool lo = (lane < 16);
        const char* gpb = (const char*)(const void*)g_P + lane * 8;
        const __half2 z = __float2half2_rn(0.f);

        #pragma unroll
        for (int p = 0; p < 8; p++) {
            const unsigned oAs = __shfl_sync(0xffffffffu, off, 2 * p);
            const unsigned oAd = __shfl_sync(0xffffffffu, off, 16 + 2 * p);
            const unsigned oBs = __shfl_sync(0xffffffffu, off, 2 * p + 1);
            const unsigned oBd = __shfl_sync(0xffffffffu, off, 17 + 2 * p);

            const uint2 sa = *(const uint2*)(gpb + oAs);
            const uint2 da = *(const uint2*)(gpb + oAd + 256);
            const uint2 sb = *(const uint2*)(gpb + oBs);
            const uint2 db = *(const uint2*)(gpb + oBd + 256);

            const unsigned wa0 = h2u(__hadd2(u2h(sa.x), u2h(da.x)));
            const unsigned wa1 = h2u(__hadd2(u2h(sa.y), u2h(da.y)));
            const unsigned wb0 = h2u(__hadd2(u2h(sb.x), u2h(db.x)));
            const unsigned wb1 = h2u(__hadd2(u2h(sb.y), u2h(db.y)));

            const unsigned t0 = lo ? wb0 : wa0;
            const unsigned t1 = lo ? wb1 : wa1;
            const unsigned o0 = __shfl_xor_sync(0xffffffffu, t0, 16);
            const unsigned o1 = __shfl_xor_sync(0xffffffffu, t1, 16);

            const __half2 w0 = u2h(lo ? wa0 : o0);
            const __half2 w1 = u2h(lo ? wa1 : o1);
            const __half2 a0 = u2h(lo ? o0 : wb0);
            const __half2 a1 = u2h(lo ? o1 : wb1);

            const __half2 h01 = __hmax2(__hadd2(__hmax2(w0, z), a0), z);
            const __half2 h23 = __hmax2(__hadd2(__hmax2(w1, z), a1), z);

            const int e_loc = warp * 16 + 2 * p + (lo ? 0 : 1);
            *(uint2*)(h1s + e_loc * H1PH + 4 * l15) = make_uint2(h2u(h01), h2u(h23));
        }
    }
    __syncthreads();

    const int bk  = (lane >> 3) & 1;
    const int bn8 = (lane >> 4) & 1;
    const int br  = lane & 7;

    // ---- Stage B: layer2 via mma, B frags via ldmatrix.trans ----
    const unsigned h1_a = sm_u32(h1s) +
        ((m0 + (lane & 15)) * H1PH + ((lane >> 4) << 3)) * 2;
    const unsigned wc_base = sm_u32(Wc);
    float acc[8][4];
    #pragma unroll
    for (int nb = 0; nb < 8; nb++)
        #pragma unroll
        for (int c = 0; c < 4; c++) acc[nb][c] = 0.f;

    #pragma unroll
    for (int kb = 0; kb < 4; kb++) {
        unsigned a0, a1, a2, a3;
        ldmat4(a0, a1, a2, a3, h1_a + kb * 32);
        #pragma unroll
        for (int nb2 = 0; nb2 < 4; nb2++) {
            const unsigned off =
                ((kb * 16 + bk * 8 + br) * H1PH + nb2 * 16 + bn8 * 8) * 2;
            unsigned b0, b1r, b2r, b3r;
            ldmat4t(b0, b1r, b2r, b3r, wc_base + off);
            mma16816(acc[2 * nb2],     a0, a1, a2, a3, b0, b1r);
            mma16816(acc[2 * nb2 + 1], a0, a1, a2, a3, b2r, b3r);
        }
    }

    {
        unsigned regs[8];
        #pragma unroll
        for (int j = 0; j < 4; j++) {
            const float2 bb = __ldg((const float2*)(b2 + 8 * j + 2 * lq));
            float v0 = fmaxf(fmaxf(acc[j][0] + bb.x, 0.f) + acc[j + 4][0], 0.f);
            float v1 = fmaxf(fmaxf(acc[j][1] + bb.y, 0.f) + acc[j + 4][1], 0.f);
            float v2 = fmaxf(fmaxf(acc[j][2] + bb.x, 0.f) + acc[j + 4][2], 0.f);
            float v3 = fmaxf(fmaxf(acc[j][3] + bb.y, 0.f) + acc[j + 4][3], 0.f);
            regs[2 * j]     = h2u(__floats2half2_rn(v0, v1));
            regs[2 * j + 1] = h2u(__floats2half2_rn(v2, v3));
        }
        const unsigned h2_a = sm_u32(h2s) +
            ((m0 + (lane & 15)) * H2PH + ((lane >> 4) << 3)) * 2;
        stmat4(h2_a,      regs[0], regs[1], regs[2], regs[3]);
        stmat4(h2_a + 32, regs[4], regs[5], regs[6], regs[7]);
    }
    __syncwarp();

    // ---- Stage C: layer3 via mma + head ----
    const unsigned h2_ra = sm_u32(h2s) +
        ((m0 + (lane & 15)) * H2PH + ((lane >> 4) << 3)) * 2;
    const unsigned w3_base = sm_u32(W3c);
    float acc3[4][4];
    #pragma unroll
    for (int nb = 0; nb < 4; nb++)
        #pragma unroll
        for (int c = 0; c < 4; c++) acc3[nb][c] = 0.f;

    #pragma unroll
    for (int kb = 0; kb < 2; kb++) {
        unsigned a0, a1, a2, a3;
        ldmat4(a0, a1, a2, a3, h2_ra + kb * 32);
        #pragma unroll
        for (int nb2 = 0; nb2 < 2; nb2++) {
            const unsigned off =
                ((kb * 16 + bk * 8 + br) * H2PH + nb2 * 16 + bn8 * 8) * 2;
            unsigned b0, b1r, b2r, b3r;
            ldmat4t(b0, b1r, b2r, b3r, w3_base + off);
            mma16816(acc3[2 * nb2],     a0, a1, a2, a3, b0, b1r);
            mma16816(acc3[2 * nb2 + 1], a0, a1, a2, a3, b2r, b3r);
        }
    }

    float pr = 0.f, pr8 = 0.f;
    #pragma unroll
    for (int j = 0; j < 2; j++) {
        const float2 bb = __ldg((const float2*)(b3 + 8 * j + 2 * lq));
        const float2 wf = __ldg((const float2*)(Wf + 8 * j + 2 * lq));
        float v0 = fmaxf(fmaxf(acc3[j][0] + bb.x, 0.f) + acc3[j + 2][0], 0.f);
        float v1 = fmaxf(fmaxf(acc3[j][1] + bb.y, 0.f) + acc3[j + 2][1], 0.f);
        float v2 = fmaxf(fmaxf(acc3[j][2] + bb.x, 0.f) + acc3[j + 2][2], 0.f);
        float v3 = fmaxf(fmaxf(acc3[j][3] + bb.y, 0.f) + acc3[j + 2][3], 0.f);
        pr  += v0 * wf.x + v1 * wf.y;
        pr8 += v2 * wf.x + v3 * wf.y;
    }
    pr  += __shfl_xor_sync(0xffffffffu, pr, 1);
    pr  += __shfl_xor_sync(0xffffffffu, pr, 2);
    pr8 += __shfl_xor_sync(0xffffffffu, pr8, 1);
    pr8 += __shfl_xor_sync(0xffffffffu, pr8, 2);

    if (lq == 0) {
        const float bfv = __ldg(bf);
        int eg = e_base + m0 + lr;
        if (eg < E)     out[eg]     = 1.f / (1.f + expf(-(pr + bfv)));
        if (eg + 8 < E) out[eg + 8] = 1.f / (1.f + expf(-(pr8 + bfv)));
    }
}

// ---------------------------------------------------------------------------
extern "C" void kernel_launch(void* const* d_in, const int* in_sizes, int n_in,
                              void* d_out, int out_size) {
    const float* x  = (const float*)d_in[0];
    const int*   ei = (const int*)d_in[1];
    const float* W1 = (const float*)d_in[2];
    const float* b1 = (const float*)d_in[3];
    const float* A1 = (const float*)d_in[4];
    const float* W2 = (const float*)d_in[5];
    const float* b2 = (const float*)d_in[6];
    const float* A2 = (const float*)d_in[7];
    const float* W3 = (const float*)d_in[8];
    const float* b3 = (const float*)d_in[9];
    const float* A3 = (const float*)d_in[10];
    const float* Wf = (const float*)d_in[11];
    const float* bf = (const float*)d_in[12];
    float* out = (float*)d_out;

    const int n_nodes = in_sizes[0] / F_DIM;
    const int E = in_sizes[1] / 2;

    const int pre_smem = (128 * APH + 128 * BPH + 128 * OPH) * 2;   // 71680
    cudaFuncSetAttribute(precompute_hmma16, cudaFuncAttributeMaxDynamicSharedMemorySize, pre_smem);
    precompute_hmma16<<<(n_nodes + 127) / 128, 256, pre_smem>>>(x, W1, A1, b1, n_nodes);

    const int smem_bytes = (9216 + 5120 + 4608 + 1280) * 2;         // 40448
    cudaFuncSetAttribute(edge_kernel10, cudaFuncAttributeMaxDynamicSharedMemorySize, smem_bytes);
    const int nb = (E + TILE_E - 1) / TILE_E;
    edge_kernel10<<<nb, 256, smem_bytes>>>(ei, W2, b2, A2, W3, b3, A3, Wf, bf, out, E);
}